// round 2
// baseline (speedup 1.0000x reference)
#include <cuda_runtime.h>
#include <cuda_bf16.h>
#include <math.h>

// ---------------- problem constants ----------------
#define BATCH 512
#define SEQL  20
#define NNODE 16
#define EPS_  32
#define HDIM  128
#define VOCAB 100000
#define NTOT  (BATCH*NNODE)        // 8192
#define NEDGE (BATCH*EPS_)         // 16384
#define NOUT  (VOCAB-1)            // 99999

// ---------------- device scratch (no allocs allowed) ----------------
__device__ float g_x[NTOT*HDIM];          // node features (updated in place by GRU)
__device__ float g_m[NTOT*HDIM];          // x @ ggnn_w
__device__ float g_agg[NTOT*HDIM];        // scatter-add aggregate
__device__ float g_gi[NTOT*3*HDIM];       // agg @ W_ih^T
__device__ float g_gh[NTOT*3*HDIM];       // x   @ W_hh^T
__device__ float g_gT[HDIM*HDIM];         // ggnn_w transposed -> [h][k]
__device__ float g_hidden[BATCH*SEQL*HDIM];
__device__ float g_ht[BATCH*HDIM];
__device__ float g_q1[BATCH*HDIM];
__device__ float g_q2[BATCH*SEQL*HDIM];
__device__ float g_afin[BATCH*HDIM];

// ---------------- generic tiled NT GEMM, K = 128 ----------------
// C[M,N] = A[M,128] * B[N,128]^T.  A,B row-major.  TM=TN=128, 256 thr, 8x8/thread.
// Accumulate with packed fma.rn.f32x2 (2 FMA / instr).
__global__ __launch_bounds__(256) void gemm_nt(
    const float* __restrict__ A, const float* __restrict__ B,
    float* __restrict__ C, int M, int N)
{
    extern __shared__ float sm[];
    float* As = sm;             // k-major: As[k*128 + m]
    float* Bs = sm + 128*128;   // k-major: Bs[k*128 + n]
    const int tid   = threadIdx.x;
    const int mBase = blockIdx.y << 7;
    const int nBase = blockIdx.x << 7;

    // load + transpose tiles.  idx -> (r = idx&127, kq = idx>>7):
    // warp threads share kq, r consecutive -> conflict-free smem stores.
    #pragma unroll
    for (int it = 0; it < 16; ++it) {
        int idx = tid + it*256;
        int r = idx & 127, kq = idx >> 7;
        float4 v = *reinterpret_cast<const float4*>(A + (size_t)(mBase + r)*128 + (kq<<2));
        As[((kq<<2)+0)*128 + r] = v.x;
        As[((kq<<2)+1)*128 + r] = v.y;
        As[((kq<<2)+2)*128 + r] = v.z;
        As[((kq<<2)+3)*128 + r] = v.w;
    }
    #pragma unroll
    for (int it = 0; it < 16; ++it) {
        int idx = tid + it*256;
        int r = idx & 127, kq = idx >> 7;
        int n = nBase + r;
        float4 v = make_float4(0.f, 0.f, 0.f, 0.f);
        if (n < N) v = *reinterpret_cast<const float4*>(B + (size_t)n*128 + (kq<<2));
        Bs[((kq<<2)+0)*128 + r] = v.x;
        Bs[((kq<<2)+1)*128 + r] = v.y;
        Bs[((kq<<2)+2)*128 + r] = v.z;
        Bs[((kq<<2)+3)*128 + r] = v.w;
    }
    __syncthreads();

    const int tx = tid & 15, ty = tid >> 4;
    const int m0 = ty << 3, n0 = tx << 3;

    unsigned long long acc[32];   // [i(m,8)][j(n-pair,4)]
    #pragma unroll
    for (int i = 0; i < 32; ++i) acc[i] = 0ULL;

    #pragma unroll 8
    for (int k = 0; k < 128; ++k) {
        const float* ap = As + k*128 + m0;
        float4 aL = *reinterpret_cast<const float4*>(ap);
        float4 aH = *reinterpret_cast<const float4*>(ap + 4);
        float av[8] = {aL.x, aL.y, aL.z, aL.w, aH.x, aH.y, aH.z, aH.w};
        unsigned long long a2[8];
        #pragma unroll
        for (int i = 0; i < 8; ++i)
            asm("mov.b64 %0, {%1, %2};" : "=l"(a2[i]) : "f"(av[i]), "f"(av[i]));
        const unsigned long long* bp =
            reinterpret_cast<const unsigned long long*>(Bs + k*128 + n0);
        unsigned long long b2[4];
        #pragma unroll
        for (int j = 0; j < 4; ++j) b2[j] = bp[j];
        #pragma unroll
        for (int i = 0; i < 8; ++i) {
            #pragma unroll
            for (int j = 0; j < 4; ++j)
                asm("fma.rn.f32x2 %0, %1, %2, %0;"
                    : "+l"(acc[i*4 + j]) : "l"(a2[i]), "l"(b2[j]));
        }
    }

    #pragma unroll
    for (int i = 0; i < 8; ++i) {
        size_t row = (size_t)(mBase + m0 + i) * (size_t)N;
        #pragma unroll
        for (int j = 0; j < 4; ++j) {
            int n = nBase + n0 + (j << 1);
            unsigned long long v = acc[i*4 + j];
            float lo = __uint_as_float((unsigned int)(v & 0xffffffffu));
            float hi = __uint_as_float((unsigned int)(v >> 32));
            if (n     < N) C[row + n]     = lo;
            if (n + 1 < N) C[row + n + 1] = hi;
        }
    }
}

// ---------------- small kernels ----------------
__global__ void prep_kernel(const float* __restrict__ ggnn) {
    int idx = blockIdx.x*256 + threadIdx.x;
    if (idx < NTOT*HDIM) g_agg[idx] = 0.f;
    if (idx < HDIM*HDIM) {
        int k = idx >> 7, h = idx & 127;
        g_gT[h*HDIM + k] = ggnn[idx];           // ggnn_w[0][k][h] -> gT[h][k]
    }
}

__global__ void gather_kernel(const int* __restrict__ items,
                              const float* __restrict__ emb) {
    int idx = blockIdx.x*256 + threadIdx.x;     // < NTOT*HDIM
    int node = idx >> 7, h = idx & 127;
    g_x[idx] = emb[(size_t)items[node]*HDIM + h];
}

__global__ void scatter_kernel(const int* __restrict__ ei) {
    int e = blockIdx.x;                          // NEDGE blocks
    int h = threadIdx.x;                         // 128
    int s = ei[e], d = ei[NEDGE + e];
    atomicAdd(&g_agg[(size_t)d*HDIM + h], g_m[(size_t)s*HDIM + h]);
}

__global__ void gru_kernel(const float* __restrict__ b_ih,
                           const float* __restrict__ b_hh) {
    int idx = blockIdx.x*256 + threadIdx.x;     // < NTOT*HDIM
    int node = idx >> 7, h = idx & 127;
    const float* gi = g_gi + (size_t)node*384;
    const float* gh = g_gh + (size_t)node*384;
    float ir = gi[h]       + b_ih[h],       hr = gh[h]       + b_hh[h];
    float iz = gi[128 + h] + b_ih[128 + h], hz = gh[128 + h] + b_hh[128 + h];
    float in_= gi[256 + h] + b_ih[256 + h], hn = gh[256 + h] + b_hh[256 + h];
    float r = 1.f/(1.f + expf(-(ir + hr)));
    float z = 1.f/(1.f + expf(-(iz + hz)));
    float n = tanhf(in_ + r*hn);
    g_x[idx] = (1.f - z)*n + z*g_x[idx];
}

__global__ void hidden_kernel(const int* __restrict__ items,
                              const int* __restrict__ seq,
                              const int* __restrict__ mask,
                              const float* __restrict__ emb) {
    int b = blockIdx.x, h = threadIdx.x;        // 512 blocks, 128 thr
    __shared__ int it_s[NNODE];
    __shared__ int sl;
    if (h < NNODE) it_s[h] = items[b*NNODE + h];
    if (h == 0) {
        int c = 0;
        for (int l = 0; l < SEQL; ++l) c += mask[b*SEQL + l];
        sl = c - 1;
    }
    __syncthreads();
    int seqlen = sl;
    for (int l = 0; l < SEQL; ++l) {
        int s = seq[b*SEQL + l];
        float v = 0.f;
        if (s != 0) {
            int found = -1;
            #pragma unroll
            for (int ns = 0; ns < NNODE; ++ns)
                if (found < 0 && it_s[ns] == s) found = ns;
            v = (found >= 0) ? g_x[(size_t)(b*NNODE + found)*HDIM + h]
                             : emb[(size_t)s*HDIM + h];
        }
        g_hidden[(size_t)(b*SEQL + l)*HDIM + h] = v;
        if (l == seqlen) g_ht[b*HDIM + h] = v;
    }
}

__device__ __forceinline__ float blockSum128(float v, float* red) {
    #pragma unroll
    for (int o = 16; o > 0; o >>= 1) v += __shfl_xor_sync(0xffffffffu, v, o);
    if ((threadIdx.x & 31) == 0) red[threadIdx.x >> 5] = v;
    __syncthreads();
    v = red[0] + red[1] + red[2] + red[3];
    __syncthreads();
    return v;
}

__global__ void attn_kernel(const int* __restrict__ mask,
                            const float* __restrict__ b1,
                            const float* __restrict__ b2,
                            const float* __restrict__ w3,
                            const float* __restrict__ Wt,
                            const float* __restrict__ bt,
                            const float* __restrict__ gamma,
                            const float* __restrict__ beta) {
    int b = blockIdx.x, h = threadIdx.x;        // 512 blocks, 128 thr
    __shared__ float hid[SEQL*HDIM];
    __shared__ float red[4];
    __shared__ float a_s[HDIM], ht_s[HDIM];
    __shared__ int   msk[SEQL];
    for (int i = h; i < SEQL*HDIM; i += 128) hid[i] = g_hidden[(size_t)b*SEQL*HDIM + i];
    if (h < SEQL) msk[h] = mask[b*SEQL + h];
    __syncthreads();

    float q1v = g_q1[b*HDIM + h] + b1[h];
    float b2v = b2[h];
    float w3v = w3[h];
    float acc = 0.f;
    for (int l = 0; l < SEQL; ++l) {
        float q2v = g_q2[(size_t)(b*SEQL + l)*HDIM + h] + b2v;
        float s = 1.f/(1.f + expf(-(q1v + q2v)));
        float alpha = blockSum128(s * w3v, red);
        if (msk[l]) acc += alpha * hid[l*HDIM + h];
    }
    int seqlen = -1;
    #pragma unroll
    for (int l = 0; l < SEQL; ++l) seqlen += msk[l];

    a_s[h]  = acc;
    ht_s[h] = hid[seqlen*HDIM + h];
    __syncthreads();

    float av = bt[h];
    const float* wr = Wt + (size_t)h*256;       // Wt: [H, 2H] row-major
    #pragma unroll 8
    for (int k = 0; k < HDIM; ++k) av += a_s[k]  * wr[k];
    #pragma unroll 8
    for (int k = 0; k < HDIM; ++k) av += ht_s[k] * wr[HDIM + k];

    float mu  = blockSum128(av, red) * (1.f/HDIM);
    float d   = av - mu;
    float var = blockSum128(d*d, red) * (1.f/HDIM);
    g_afin[b*HDIM + h] = d * rsqrtf(var + 1e-5f) * gamma[h] + beta[h];
}

// ---------------- launch ----------------
extern "C" void kernel_launch(void* const* d_in, const int* in_sizes, int n_in,
                              void* d_out, int out_size) {
    const int*   items = (const int*)  d_in[0];
    const int*   eidx  = (const int*)  d_in[1];
    const int*   seq   = (const int*)  d_in[2];
    const int*   mask  = (const int*)  d_in[3];
    const float* emb   = (const float*)d_in[4];
    const float* ggnn  = (const float*)d_in[5];
    const float* Wih   = (const float*)d_in[6];
    const float* Whh   = (const float*)d_in[7];
    const float* bih   = (const float*)d_in[8];
    const float* bhh   = (const float*)d_in[9];
    const float* W1    = (const float*)d_in[10];
    const float* b1    = (const float*)d_in[11];
    const float* W2    = (const float*)d_in[12];
    const float* b2    = (const float*)d_in[13];
    const float* w3    = (const float*)d_in[14];
    const float* Wt    = (const float*)d_in[15];
    const float* bt    = (const float*)d_in[16];
    const float* gamma = (const float*)d_in[17];
    const float* beta  = (const float*)d_in[18];
    float* out = (float*)d_out;

    float *px, *pm, *pagg, *pgi, *pgh, *pgT, *phid, *pht, *pq1, *pq2, *pafin;
    cudaGetSymbolAddress((void**)&px,    g_x);
    cudaGetSymbolAddress((void**)&pm,    g_m);
    cudaGetSymbolAddress((void**)&pagg,  g_agg);
    cudaGetSymbolAddress((void**)&pgi,   g_gi);
    cudaGetSymbolAddress((void**)&pgh,   g_gh);
    cudaGetSymbolAddress((void**)&pgT,   g_gT);
    cudaGetSymbolAddress((void**)&phid,  g_hidden);
    cudaGetSymbolAddress((void**)&pht,   g_ht);
    cudaGetSymbolAddress((void**)&pq1,   g_q1);
    cudaGetSymbolAddress((void**)&pq2,   g_q2);
    cudaGetSymbolAddress((void**)&pafin, g_afin);

    const int SMEM = 2*128*128*4;  // 128 KB
    cudaFuncSetAttribute(gemm_nt, cudaFuncAttributeMaxDynamicSharedMemorySize, SMEM);

    prep_kernel  <<<4096, 256>>>(ggnn);
    gather_kernel<<<4096, 256>>>(items, emb);
    gemm_nt<<<dim3(1, 64),  256, SMEM>>>(px,   pgT, pm,  NTOT,  HDIM);   // m = x @ ggnn_w
    scatter_kernel<<<NEDGE, 128>>>(eidx);
    gemm_nt<<<dim3(3, 64),  256, SMEM>>>(pagg, Wih, pgi, NTOT,  3*HDIM); // gi
    gemm_nt<<<dim3(3, 64),  256, SMEM>>>(px,   Whh, pgh, NTOT,  3*HDIM); // gh
    gru_kernel   <<<4096, 256>>>(bih, bhh);
    hidden_kernel<<<BATCH, 128>>>(items, seq, mask, emb);
    gemm_nt<<<dim3(1, 4),   256, SMEM>>>(pht,  W1,  pq1, BATCH, HDIM);   // q1
    gemm_nt<<<dim3(1, 80),  256, SMEM>>>(phid, W2,  pq2, BATCH*SEQL, HDIM); // q2
    attn_kernel  <<<BATCH, 128>>>(mask, b1, b2, w3, Wt, bt, gamma, beta);
    gemm_nt<<<dim3((NOUT + 127)/128, 4), 256, SMEM>>>(pafin, emb + HDIM, out, BATCH, NOUT);
}

// round 3
// speedup vs baseline: 1.0001x; 1.0001x over previous
#include <cuda_runtime.h>
#include <cuda_bf16.h>
#include <math.h>

// ---------------- problem constants ----------------
#define BATCH 512
#define SEQL  20
#define NNODE 16
#define EPS_  32
#define HDIM  128
#define VOCAB 100000
#define NTOT  (BATCH*NNODE)        // 8192
#define NEDGE (BATCH*EPS_)         // 16384
#define NOUT  (VOCAB-1)            // 99999

// ---------------- device scratch (no allocs allowed) ----------------
__device__ float g_x[NTOT*HDIM];          // node features (updated in place by GRU)
__device__ float g_m[NTOT*HDIM];          // x @ ggnn_w
__device__ float g_agg[NTOT*HDIM];        // scatter-add aggregate
__device__ float g_gi[NTOT*3*HDIM];       // agg @ W_ih^T
__device__ float g_gh[NTOT*3*HDIM];       // x   @ W_hh^T
__device__ float g_gT[HDIM*HDIM];         // ggnn_w transposed -> [h][k]
__device__ float g_hidden[BATCH*SEQL*HDIM];
__device__ float g_ht[BATCH*HDIM];
__device__ float g_q1[BATCH*HDIM];
__device__ float g_q2[BATCH*SEQL*HDIM];
__device__ float g_afin[BATCH*HDIM];

// ---------------- generic tiled NT GEMM, K = 128 ----------------
// C[M,N] = A[M,128] * B[N,128]^T.  A,B row-major.  TM=TN=128, 256 thr, 8x8/thread.
// Accumulate with packed fma.rn.f32x2 (2 FMA / instr).
__global__ __launch_bounds__(256) void gemm_nt(
    const float* __restrict__ A, const float* __restrict__ B,
    float* __restrict__ C, int M, int N)
{
    extern __shared__ float sm[];
    float* As = sm;             // k-major: As[k*128 + m]
    float* Bs = sm + 128*128;   // k-major: Bs[k*128 + n]
    const int tid   = threadIdx.x;
    const int mBase = blockIdx.y << 7;
    const int nBase = blockIdx.x << 7;

    // load + transpose tiles.  idx -> (r = idx&127, kq = idx>>7):
    // warp threads share kq, r consecutive -> conflict-free smem stores.
    #pragma unroll
    for (int it = 0; it < 16; ++it) {
        int idx = tid + it*256;
        int r = idx & 127, kq = idx >> 7;
        float4 v = *reinterpret_cast<const float4*>(A + (size_t)(mBase + r)*128 + (kq<<2));
        As[((kq<<2)+0)*128 + r] = v.x;
        As[((kq<<2)+1)*128 + r] = v.y;
        As[((kq<<2)+2)*128 + r] = v.z;
        As[((kq<<2)+3)*128 + r] = v.w;
    }
    #pragma unroll
    for (int it = 0; it < 16; ++it) {
        int idx = tid + it*256;
        int r = idx & 127, kq = idx >> 7;
        int n = nBase + r;
        float4 v = make_float4(0.f, 0.f, 0.f, 0.f);
        if (n < N) v = *reinterpret_cast<const float4*>(B + (size_t)n*128 + (kq<<2));
        Bs[((kq<<2)+0)*128 + r] = v.x;
        Bs[((kq<<2)+1)*128 + r] = v.y;
        Bs[((kq<<2)+2)*128 + r] = v.z;
        Bs[((kq<<2)+3)*128 + r] = v.w;
    }
    __syncthreads();

    const int tx = tid & 15, ty = tid >> 4;
    const int m0 = ty << 3, n0 = tx << 3;

    unsigned long long acc[32];   // [i(m,8)][j(n-pair,4)]
    #pragma unroll
    for (int i = 0; i < 32; ++i) acc[i] = 0ULL;

    #pragma unroll 8
    for (int k = 0; k < 128; ++k) {
        const float* ap = As + k*128 + m0;
        float4 aL = *reinterpret_cast<const float4*>(ap);
        float4 aH = *reinterpret_cast<const float4*>(ap + 4);
        float av[8] = {aL.x, aL.y, aL.z, aL.w, aH.x, aH.y, aH.z, aH.w};
        unsigned long long a2[8];
        #pragma unroll
        for (int i = 0; i < 8; ++i)
            asm("mov.b64 %0, {%1, %2};" : "=l"(a2[i]) : "f"(av[i]), "f"(av[i]));
        const unsigned long long* bp =
            reinterpret_cast<const unsigned long long*>(Bs + k*128 + n0);
        unsigned long long b2[4];
        #pragma unroll
        for (int j = 0; j < 4; ++j) b2[j] = bp[j];
        #pragma unroll
        for (int i = 0; i < 8; ++i) {
            #pragma unroll
            for (int j = 0; j < 4; ++j)
                asm("fma.rn.f32x2 %0, %1, %2, %0;"
                    : "+l"(acc[i*4 + j]) : "l"(a2[i]), "l"(b2[j]));
        }
    }

    #pragma unroll
    for (int i = 0; i < 8; ++i) {
        size_t row = (size_t)(mBase + m0 + i) * (size_t)N;
        #pragma unroll
        for (int j = 0; j < 4; ++j) {
            int n = nBase + n0 + (j << 1);
            unsigned long long v = acc[i*4 + j];
            float lo = __uint_as_float((unsigned int)(v & 0xffffffffu));
            float hi = __uint_as_float((unsigned int)(v >> 32));
            if (n     < N) C[row + n]     = lo;
            if (n + 1 < N) C[row + n + 1] = hi;
        }
    }
}

// ---------------- small kernels ----------------
__global__ void prep_kernel(const float* __restrict__ ggnn) {
    int idx = blockIdx.x*256 + threadIdx.x;
    if (idx < NTOT*HDIM) g_agg[idx] = 0.f;
    if (idx < HDIM*HDIM) {
        int k = idx >> 7, h = idx & 127;
        g_gT[h*HDIM + k] = ggnn[idx];           // ggnn_w[0][k][h] -> gT[h][k]
    }
}

__global__ void gather_kernel(const int* __restrict__ items,
                              const float* __restrict__ emb) {
    int idx = blockIdx.x*256 + threadIdx.x;     // < NTOT*HDIM
    int node = idx >> 7, h = idx & 127;
    g_x[idx] = emb[(size_t)items[node]*HDIM + h];
}

__global__ void scatter_kernel(const int* __restrict__ ei) {
    int e = blockIdx.x;                          // NEDGE blocks
    int h = threadIdx.x;                         // 128
    int s = ei[e], d = ei[NEDGE + e];
    atomicAdd(&g_agg[(size_t)d*HDIM + h], g_m[(size_t)s*HDIM + h]);
}

__global__ void gru_kernel(const float* __restrict__ b_ih,
                           const float* __restrict__ b_hh) {
    int idx = blockIdx.x*256 + threadIdx.x;     // < NTOT*HDIM
    int node = idx >> 7, h = idx & 127;
    const float* gi = g_gi + (size_t)node*384;
    const float* gh = g_gh + (size_t)node*384;
    float ir = gi[h]       + b_ih[h],       hr = gh[h]       + b_hh[h];
    float iz = gi[128 + h] + b_ih[128 + h], hz = gh[128 + h] + b_hh[128 + h];
    float in_= gi[256 + h] + b_ih[256 + h], hn = gh[256 + h] + b_hh[256 + h];
    float r = 1.f/(1.f + expf(-(ir + hr)));
    float z = 1.f/(1.f + expf(-(iz + hz)));
    float n = tanhf(in_ + r*hn);
    g_x[idx] = (1.f - z)*n + z*g_x[idx];
}

__global__ void hidden_kernel(const int* __restrict__ items,
                              const int* __restrict__ seq,
                              const int* __restrict__ mask,
                              const float* __restrict__ emb) {
    int b = blockIdx.x, h = threadIdx.x;        // 512 blocks, 128 thr
    __shared__ int it_s[NNODE];
    __shared__ int sl;
    if (h < NNODE) it_s[h] = items[b*NNODE + h];
    if (h == 0) {
        int c = 0;
        for (int l = 0; l < SEQL; ++l) c += mask[b*SEQL + l];
        sl = c - 1;
    }
    __syncthreads();
    int seqlen = sl;
    for (int l = 0; l < SEQL; ++l) {
        int s = seq[b*SEQL + l];
        float v = 0.f;
        if (s != 0) {
            int found = -1;
            #pragma unroll
            for (int ns = 0; ns < NNODE; ++ns)
                if (found < 0 && it_s[ns] == s) found = ns;
            v = (found >= 0) ? g_x[(size_t)(b*NNODE + found)*HDIM + h]
                             : emb[(size_t)s*HDIM + h];
        }
        g_hidden[(size_t)(b*SEQL + l)*HDIM + h] = v;
        if (l == seqlen) g_ht[b*HDIM + h] = v;
    }
}

__device__ __forceinline__ float blockSum128(float v, float* red) {
    #pragma unroll
    for (int o = 16; o > 0; o >>= 1) v += __shfl_xor_sync(0xffffffffu, v, o);
    if ((threadIdx.x & 31) == 0) red[threadIdx.x >> 5] = v;
    __syncthreads();
    v = red[0] + red[1] + red[2] + red[3];
    __syncthreads();
    return v;
}

__global__ void attn_kernel(const int* __restrict__ mask,
                            const float* __restrict__ b1,
                            const float* __restrict__ b2,
                            const float* __restrict__ w3,
                            const float* __restrict__ Wt,
                            const float* __restrict__ bt,
                            const float* __restrict__ gamma,
                            const float* __restrict__ beta) {
    int b = blockIdx.x, h = threadIdx.x;        // 512 blocks, 128 thr
    __shared__ float hid[SEQL*HDIM];
    __shared__ float red[4];
    __shared__ float a_s[HDIM], ht_s[HDIM];
    __shared__ int   msk[SEQL];
    for (int i = h; i < SEQL*HDIM; i += 128) hid[i] = g_hidden[(size_t)b*SEQL*HDIM + i];
    if (h < SEQL) msk[h] = mask[b*SEQL + h];
    __syncthreads();

    float q1v = g_q1[b*HDIM + h] + b1[h];
    float b2v = b2[h];
    float w3v = w3[h];
    float acc = 0.f;
    for (int l = 0; l < SEQL; ++l) {
        float q2v = g_q2[(size_t)(b*SEQL + l)*HDIM + h] + b2v;
        float s = 1.f/(1.f + expf(-(q1v + q2v)));
        float alpha = blockSum128(s * w3v, red);
        if (msk[l]) acc += alpha * hid[l*HDIM + h];
    }
    int seqlen = -1;
    #pragma unroll
    for (int l = 0; l < SEQL; ++l) seqlen += msk[l];

    a_s[h]  = acc;
    ht_s[h] = hid[seqlen*HDIM + h];
    __syncthreads();

    float av = bt[h];
    const float* wr = Wt + (size_t)h*256;       // Wt: [H, 2H] row-major
    #pragma unroll 8
    for (int k = 0; k < HDIM; ++k) av += a_s[k]  * wr[k];
    #pragma unroll 8
    for (int k = 0; k < HDIM; ++k) av += ht_s[k] * wr[HDIM + k];

    float mu  = blockSum128(av, red) * (1.f/HDIM);
    float d   = av - mu;
    float var = blockSum128(d*d, red) * (1.f/HDIM);
    g_afin[b*HDIM + h] = d * rsqrtf(var + 1e-5f) * gamma[h] + beta[h];
}

// ---------------- launch ----------------
extern "C" void kernel_launch(void* const* d_in, const int* in_sizes, int n_in,
                              void* d_out, int out_size) {
    const int*   items = (const int*)  d_in[0];
    const int*   eidx  = (const int*)  d_in[1];
    const int*   seq   = (const int*)  d_in[2];
    const int*   mask  = (const int*)  d_in[3];
    const float* emb   = (const float*)d_in[4];
    const float* ggnn  = (const float*)d_in[5];
    const float* Wih   = (const float*)d_in[6];
    const float* Whh   = (const float*)d_in[7];
    const float* bih   = (const float*)d_in[8];
    const float* bhh   = (const float*)d_in[9];
    const float* W1    = (const float*)d_in[10];
    const float* b1    = (const float*)d_in[11];
    const float* W2    = (const float*)d_in[12];
    const float* b2    = (const float*)d_in[13];
    const float* w3    = (const float*)d_in[14];
    const float* Wt    = (const float*)d_in[15];
    const float* bt    = (const float*)d_in[16];
    const float* gamma = (const float*)d_in[17];
    const float* beta  = (const float*)d_in[18];
    float* out = (float*)d_out;

    float *px, *pm, *pagg, *pgi, *pgh, *pgT, *phid, *pht, *pq1, *pq2, *pafin;
    cudaGetSymbolAddress((void**)&px,    g_x);
    cudaGetSymbolAddress((void**)&pm,    g_m);
    cudaGetSymbolAddress((void**)&pagg,  g_agg);
    cudaGetSymbolAddress((void**)&pgi,   g_gi);
    cudaGetSymbolAddress((void**)&pgh,   g_gh);
    cudaGetSymbolAddress((void**)&pgT,   g_gT);
    cudaGetSymbolAddress((void**)&phid,  g_hidden);
    cudaGetSymbolAddress((void**)&pht,   g_ht);
    cudaGetSymbolAddress((void**)&pq1,   g_q1);
    cudaGetSymbolAddress((void**)&pq2,   g_q2);
    cudaGetSymbolAddress((void**)&pafin, g_afin);

    const int SMEM = 2*128*128*4;  // 128 KB
    cudaFuncSetAttribute(gemm_nt, cudaFuncAttributeMaxDynamicSharedMemorySize, SMEM);

    prep_kernel  <<<4096, 256>>>(ggnn);
    gather_kernel<<<4096, 256>>>(items, emb);
    gemm_nt<<<dim3(1, 64),  256, SMEM>>>(px,   pgT, pm,  NTOT,  HDIM);   // m = x @ ggnn_w
    scatter_kernel<<<NEDGE, 128>>>(eidx);
    gemm_nt<<<dim3(3, 64),  256, SMEM>>>(pagg, Wih, pgi, NTOT,  3*HDIM); // gi
    gemm_nt<<<dim3(3, 64),  256, SMEM>>>(px,   Whh, pgh, NTOT,  3*HDIM); // gh
    gru_kernel   <<<4096, 256>>>(bih, bhh);
    hidden_kernel<<<BATCH, 128>>>(items, seq, mask, emb);
    gemm_nt<<<dim3(1, 4),   256, SMEM>>>(pht,  W1,  pq1, BATCH, HDIM);   // q1
    gemm_nt<<<dim3(1, 80),  256, SMEM>>>(phid, W2,  pq2, BATCH*SEQL, HDIM); // q2
    attn_kernel  <<<BATCH, 128>>>(mask, b1, b2, w3, Wt, bt, gamma, beta);
    gemm_nt<<<dim3((NOUT + 127)/128, 4), 256, SMEM>>>(pafin, emb + HDIM, out, BATCH, NOUT);
}

// round 4
// speedup vs baseline: 1.0010x; 1.0008x over previous
#include <cuda_runtime.h>
#include <cuda_bf16.h>
#include <math.h>

// ---------------- problem constants ----------------
#define BATCH 512
#define SEQL  20
#define NNODE 16
#define EPS_  32
#define HDIM  128
#define VOCAB 100000
#define NTOT  (BATCH*NNODE)        // 8192
#define NEDGE (BATCH*EPS_)         // 16384
#define NOUT  (VOCAB-1)            // 99999

// ---------------- device scratch (no allocs allowed) ----------------
__device__ float g_x[NTOT*HDIM];          // node features (updated in place by GRU)
__device__ float g_m[NTOT*HDIM];          // x @ ggnn_w
__device__ float g_agg[NTOT*HDIM];        // scatter-add aggregate
__device__ float g_gi[NTOT*3*HDIM];       // agg @ W_ih^T
__device__ float g_gh[NTOT*3*HDIM];       // x   @ W_hh^T
__device__ float g_gT[HDIM*HDIM];         // ggnn_w transposed -> [h][k]
__device__ float g_hidden[BATCH*SEQL*HDIM];
__device__ float g_ht[BATCH*HDIM];
__device__ float g_q1[BATCH*HDIM];
__device__ float g_q2[BATCH*SEQL*HDIM];
__device__ float g_afin[BATCH*HDIM];

// ---------------- generic tiled NT GEMM, K = 128 ----------------
// C[M,N] = A[M,128] * B[N,128]^T.  A,B row-major.  TM=TN=128, 256 thr, 8x8/thread.
// Accumulate with packed fma.rn.f32x2 (2 FMA / instr).
__global__ __launch_bounds__(256) void gemm_nt(
    const float* __restrict__ A, const float* __restrict__ B,
    float* __restrict__ C, int M, int N)
{
    extern __shared__ float sm[];
    float* As = sm;             // k-major: As[k*128 + m]
    float* Bs = sm + 128*128;   // k-major: Bs[k*128 + n]
    const int tid   = threadIdx.x;
    const int mBase = blockIdx.y << 7;
    const int nBase = blockIdx.x << 7;

    // load + transpose tiles.  idx -> (r = idx&127, kq = idx>>7):
    // warp threads share kq, r consecutive -> conflict-free smem stores.
    #pragma unroll
    for (int it = 0; it < 16; ++it) {
        int idx = tid + it*256;
        int r = idx & 127, kq = idx >> 7;
        float4 v = *reinterpret_cast<const float4*>(A + (size_t)(mBase + r)*128 + (kq<<2));
        As[((kq<<2)+0)*128 + r] = v.x;
        As[((kq<<2)+1)*128 + r] = v.y;
        As[((kq<<2)+2)*128 + r] = v.z;
        As[((kq<<2)+3)*128 + r] = v.w;
    }
    #pragma unroll
    for (int it = 0; it < 16; ++it) {
        int idx = tid + it*256;
        int r = idx & 127, kq = idx >> 7;
        int n = nBase + r;
        float4 v = make_float4(0.f, 0.f, 0.f, 0.f);
        if (n < N) v = *reinterpret_cast<const float4*>(B + (size_t)n*128 + (kq<<2));
        Bs[((kq<<2)+0)*128 + r] = v.x;
        Bs[((kq<<2)+1)*128 + r] = v.y;
        Bs[((kq<<2)+2)*128 + r] = v.z;
        Bs[((kq<<2)+3)*128 + r] = v.w;
    }
    __syncthreads();

    const int tx = tid & 15, ty = tid >> 4;
    const int m0 = ty << 3, n0 = tx << 3;

    unsigned long long acc[32];   // [i(m,8)][j(n-pair,4)]
    #pragma unroll
    for (int i = 0; i < 32; ++i) acc[i] = 0ULL;

    #pragma unroll 8
    for (int k = 0; k < 128; ++k) {
        const float* ap = As + k*128 + m0;
        float4 aL = *reinterpret_cast<const float4*>(ap);
        float4 aH = *reinterpret_cast<const float4*>(ap + 4);
        float av[8] = {aL.x, aL.y, aL.z, aL.w, aH.x, aH.y, aH.z, aH.w};
        unsigned long long a2[8];
        #pragma unroll
        for (int i = 0; i < 8; ++i)
            asm("mov.b64 %0, {%1, %2};" : "=l"(a2[i]) : "f"(av[i]), "f"(av[i]));
        const unsigned long long* bp =
            reinterpret_cast<const unsigned long long*>(Bs + k*128 + n0);
        unsigned long long b2[4];
        #pragma unroll
        for (int j = 0; j < 4; ++j) b2[j] = bp[j];
        #pragma unroll
        for (int i = 0; i < 8; ++i) {
            #pragma unroll
            for (int j = 0; j < 4; ++j)
                asm("fma.rn.f32x2 %0, %1, %2, %0;"
                    : "+l"(acc[i*4 + j]) : "l"(a2[i]), "l"(b2[j]));
        }
    }

    #pragma unroll
    for (int i = 0; i < 8; ++i) {
        size_t row = (size_t)(mBase + m0 + i) * (size_t)N;
        #pragma unroll
        for (int j = 0; j < 4; ++j) {
            int n = nBase + n0 + (j << 1);
            unsigned long long v = acc[i*4 + j];
            float lo = __uint_as_float((unsigned int)(v & 0xffffffffu));
            float hi = __uint_as_float((unsigned int)(v >> 32));
            if (n     < N) C[row + n]     = lo;
            if (n + 1 < N) C[row + n + 1] = hi;
        }
    }
}

// ---------------- small kernels ----------------
__global__ void prep_kernel(const float* __restrict__ ggnn) {
    int idx = blockIdx.x*256 + threadIdx.x;
    if (idx < NTOT*HDIM) g_agg[idx] = 0.f;
    if (idx < HDIM*HDIM) {
        int k = idx >> 7, h = idx & 127;
        g_gT[h*HDIM + k] = ggnn[idx];           // ggnn_w[0][k][h] -> gT[h][k]
    }
}

__global__ void gather_kernel(const int* __restrict__ items,
                              const float* __restrict__ emb) {
    int idx = blockIdx.x*256 + threadIdx.x;     // < NTOT*HDIM
    int node = idx >> 7, h = idx & 127;
    g_x[idx] = emb[(size_t)items[node]*HDIM + h];
}

__global__ void scatter_kernel(const int* __restrict__ ei) {
    int e = blockIdx.x;                          // NEDGE blocks
    int h = threadIdx.x;                         // 128
    int s = ei[e], d = ei[NEDGE + e];
    atomicAdd(&g_agg[(size_t)d*HDIM + h], g_m[(size_t)s*HDIM + h]);
}

__global__ void gru_kernel(const float* __restrict__ b_ih,
                           const float* __restrict__ b_hh) {
    int idx = blockIdx.x*256 + threadIdx.x;     // < NTOT*HDIM
    int node = idx >> 7, h = idx & 127;
    const float* gi = g_gi + (size_t)node*384;
    const float* gh = g_gh + (size_t)node*384;
    float ir = gi[h]       + b_ih[h],       hr = gh[h]       + b_hh[h];
    float iz = gi[128 + h] + b_ih[128 + h], hz = gh[128 + h] + b_hh[128 + h];
    float in_= gi[256 + h] + b_ih[256 + h], hn = gh[256 + h] + b_hh[256 + h];
    float r = 1.f/(1.f + expf(-(ir + hr)));
    float z = 1.f/(1.f + expf(-(iz + hz)));
    float n = tanhf(in_ + r*hn);
    g_x[idx] = (1.f - z)*n + z*g_x[idx];
}

__global__ void hidden_kernel(const int* __restrict__ items,
                              const int* __restrict__ seq,
                              const int* __restrict__ mask,
                              const float* __restrict__ emb) {
    int b = blockIdx.x, h = threadIdx.x;        // 512 blocks, 128 thr
    __shared__ int it_s[NNODE];
    __shared__ int sl;
    if (h < NNODE) it_s[h] = items[b*NNODE + h];
    if (h == 0) {
        int c = 0;
        for (int l = 0; l < SEQL; ++l) c += mask[b*SEQL + l];
        sl = c - 1;
    }
    __syncthreads();
    int seqlen = sl;
    for (int l = 0; l < SEQL; ++l) {
        int s = seq[b*SEQL + l];
        float v = 0.f;
        if (s != 0) {
            int found = -1;
            #pragma unroll
            for (int ns = 0; ns < NNODE; ++ns)
                if (found < 0 && it_s[ns] == s) found = ns;
            v = (found >= 0) ? g_x[(size_t)(b*NNODE + found)*HDIM + h]
                             : emb[(size_t)s*HDIM + h];
        }
        g_hidden[(size_t)(b*SEQL + l)*HDIM + h] = v;
        if (l == seqlen) g_ht[b*HDIM + h] = v;
    }
}

__device__ __forceinline__ float blockSum128(float v, float* red) {
    #pragma unroll
    for (int o = 16; o > 0; o >>= 1) v += __shfl_xor_sync(0xffffffffu, v, o);
    if ((threadIdx.x & 31) == 0) red[threadIdx.x >> 5] = v;
    __syncthreads();
    v = red[0] + red[1] + red[2] + red[3];
    __syncthreads();
    return v;
}

__global__ void attn_kernel(const int* __restrict__ mask,
                            const float* __restrict__ b1,
                            const float* __restrict__ b2,
                            const float* __restrict__ w3,
                            const float* __restrict__ Wt,
                            const float* __restrict__ bt,
                            const float* __restrict__ gamma,
                            const float* __restrict__ beta) {
    int b = blockIdx.x, h = threadIdx.x;        // 512 blocks, 128 thr
    __shared__ float hid[SEQL*HDIM];
    __shared__ float red[4];
    __shared__ float a_s[HDIM], ht_s[HDIM];
    __shared__ int   msk[SEQL];
    for (int i = h; i < SEQL*HDIM; i += 128) hid[i] = g_hidden[(size_t)b*SEQL*HDIM + i];
    if (h < SEQL) msk[h] = mask[b*SEQL + h];
    __syncthreads();

    float q1v = g_q1[b*HDIM + h] + b1[h];
    float b2v = b2[h];
    float w3v = w3[h];
    float acc = 0.f;
    for (int l = 0; l < SEQL; ++l) {
        float q2v = g_q2[(size_t)(b*SEQL + l)*HDIM + h] + b2v;
        float s = 1.f/(1.f + expf(-(q1v + q2v)));
        float alpha = blockSum128(s * w3v, red);
        if (msk[l]) acc += alpha * hid[l*HDIM + h];
    }
    int seqlen = -1;
    #pragma unroll
    for (int l = 0; l < SEQL; ++l) seqlen += msk[l];

    a_s[h]  = acc;
    ht_s[h] = hid[seqlen*HDIM + h];
    __syncthreads();

    float av = bt[h];
    const float* wr = Wt + (size_t)h*256;       // Wt: [H, 2H] row-major
    #pragma unroll 8
    for (int k = 0; k < HDIM; ++k) av += a_s[k]  * wr[k];
    #pragma unroll 8
    for (int k = 0; k < HDIM; ++k) av += ht_s[k] * wr[HDIM + k];

    float mu  = blockSum128(av, red) * (1.f/HDIM);
    float d   = av - mu;
    float var = blockSum128(d*d, red) * (1.f/HDIM);
    g_afin[b*HDIM + h] = d * rsqrtf(var + 1e-5f) * gamma[h] + beta[h];
}

// ---------------- launch ----------------
extern "C" void kernel_launch(void* const* d_in, const int* in_sizes, int n_in,
                              void* d_out, int out_size) {
    const int*   items = (const int*)  d_in[0];
    const int*   eidx  = (const int*)  d_in[1];
    const int*   seq   = (const int*)  d_in[2];
    const int*   mask  = (const int*)  d_in[3];
    const float* emb   = (const float*)d_in[4];
    const float* ggnn  = (const float*)d_in[5];
    const float* Wih   = (const float*)d_in[6];
    const float* Whh   = (const float*)d_in[7];
    const float* bih   = (const float*)d_in[8];
    const float* bhh   = (const float*)d_in[9];
    const float* W1    = (const float*)d_in[10];
    const float* b1    = (const float*)d_in[11];
    const float* W2    = (const float*)d_in[12];
    const float* b2    = (const float*)d_in[13];
    const float* w3    = (const float*)d_in[14];
    const float* Wt    = (const float*)d_in[15];
    const float* bt    = (const float*)d_in[16];
    const float* gamma = (const float*)d_in[17];
    const float* beta  = (const float*)d_in[18];
    float* out = (float*)d_out;

    float *px, *pm, *pagg, *pgi, *pgh, *pgT, *phid, *pht, *pq1, *pq2, *pafin;
    cudaGetSymbolAddress((void**)&px,    g_x);
    cudaGetSymbolAddress((void**)&pm,    g_m);
    cudaGetSymbolAddress((void**)&pagg,  g_agg);
    cudaGetSymbolAddress((void**)&pgi,   g_gi);
    cudaGetSymbolAddress((void**)&pgh,   g_gh);
    cudaGetSymbolAddress((void**)&pgT,   g_gT);
    cudaGetSymbolAddress((void**)&phid,  g_hidden);
    cudaGetSymbolAddress((void**)&pht,   g_ht);
    cudaGetSymbolAddress((void**)&pq1,   g_q1);
    cudaGetSymbolAddress((void**)&pq2,   g_q2);
    cudaGetSymbolAddress((void**)&pafin, g_afin);

    const int SMEM = 2*128*128*4;  // 128 KB
    cudaFuncSetAttribute(gemm_nt, cudaFuncAttributeMaxDynamicSharedMemorySize, SMEM);

    prep_kernel  <<<4096, 256>>>(ggnn);
    gather_kernel<<<4096, 256>>>(items, emb);
    gemm_nt<<<dim3(1, 64),  256, SMEM>>>(px,   pgT, pm,  NTOT,  HDIM);   // m = x @ ggnn_w
    scatter_kernel<<<NEDGE, 128>>>(eidx);
    gemm_nt<<<dim3(3, 64),  256, SMEM>>>(pagg, Wih, pgi, NTOT,  3*HDIM); // gi
    gemm_nt<<<dim3(3, 64),  256, SMEM>>>(px,   Whh, pgh, NTOT,  3*HDIM); // gh
    gru_kernel   <<<4096, 256>>>(bih, bhh);
    hidden_kernel<<<BATCH, 128>>>(items, seq, mask, emb);
    gemm_nt<<<dim3(1, 4),   256, SMEM>>>(pht,  W1,  pq1, BATCH, HDIM);   // q1
    gemm_nt<<<dim3(1, 80),  256, SMEM>>>(phid, W2,  pq2, BATCH*SEQL, HDIM); // q2
    attn_kernel  <<<BATCH, 128>>>(mask, b1, b2, w3, Wt, bt, gamma, beta);
    gemm_nt<<<dim3((NOUT + 127)/128, 4), 256, SMEM>>>(pafin, emb + HDIM, out, BATCH, NOUT);
}

// round 6
// speedup vs baseline: 1.9847x; 1.9828x over previous
#include <cuda_runtime.h>
#include <cuda_bf16.h>
#include <math.h>
#include <cstdint>

// ---------------- problem constants ----------------
#define BATCH 512
#define SEQL  20
#define NNODE 16
#define EPS_  32
#define HDIM  128
#define VOCAB 100000
#define NTOT  (BATCH*NNODE)        // 8192
#define NEDGE (BATCH*EPS_)         // 16384
#define NOUT  (VOCAB-1)            // 99999

// ---------------- device scratch (no allocs allowed) ----------------
__device__ float g_x[NTOT*HDIM];
__device__ float g_m[NTOT*HDIM];
__device__ float g_agg[NTOT*HDIM];
__device__ float g_gi[NTOT*3*HDIM];
__device__ float g_gh[NTOT*3*HDIM];
__device__ float g_gT[HDIM*HDIM];
__device__ float g_hidden[BATCH*SEQL*HDIM];
__device__ float g_ht[BATCH*HDIM];
__device__ float g_q1[BATCH*HDIM];
__device__ float g_q2[BATCH*SEQL*HDIM];
__device__ float g_afin[BATCH*HDIM];

// ---------------- split-bf16 tensor-core GEMM (mma.sync, K=128) ----------------
// C[M,N] = A[M,128] * B[N,128]^T, fp32 in/out.
// Accuracy: x = hi + lo (exact mantissa split), C ~= Ahi*Bhi + Ahi*Blo + Alo*Bhi.
// smem tiles: bf16 [128 rows][128 cols], rows padded to 272B (136 bf16):
// bank(row,tig) = (68*row + tig) mod 32 = (4*row + tig) mod 32 -> conflict-free frag loads.
#define ROWB     272
#define SM_AHI   0
#define SM_ALO   34816
#define SM_BHI   69632
#define SM_BLO   104448
#define SM_TOTAL 139264

// hi = bf16 bits via truncation (exact split: lo = x - hi representable in fp32)
__device__ __forceinline__ void split2(float x, float y, uint32_t& hi, uint32_t& lo) {
    uint32_t ux = __float_as_uint(x), uy = __float_as_uint(y);
    hi = __byte_perm(ux, uy, 0x7632);                    // {x.hi16, y.hi16}
    float lx = x - __uint_as_float(ux & 0xffff0000u);
    float ly = y - __uint_as_float(uy & 0xffff0000u);
    __nv_bfloat162 t = __floats2bfloat162_rn(lx, ly);
    lo = *reinterpret_cast<uint32_t*>(&t);
}

#define MMA_BF16(d, a, b)                                                        \
    asm volatile("mma.sync.aligned.m16n8k16.row.col.f32.bf16.bf16.f32 "         \
                 "{%0,%1,%2,%3}, {%4,%5,%6,%7}, {%8,%9}, {%0,%1,%2,%3};"        \
                 : "+f"((d)[0]), "+f"((d)[1]), "+f"((d)[2]), "+f"((d)[3])        \
                 : "r"((a)[0]), "r"((a)[1]), "r"((a)[2]), "r"((a)[3]),           \
                   "r"((b)[0]), "r"((b)[1]))

__global__ __launch_bounds__(256) void gemm_tc(
    const float* __restrict__ A, const float* __restrict__ B,
    float* __restrict__ C, int N)
{
    extern __shared__ char sm[];
    const int tid  = threadIdx.x, wid = tid >> 5, lane = tid & 31;
    const int g    = lane >> 2, tig = lane & 3;
    const int mBase = blockIdx.y << 7, nBase = blockIdx.x << 7;

    // ---- load fp32 tiles, split into bf16 hi/lo, store padded-row-major ----
    #pragma unroll
    for (int it = 0; it < 16; ++it) {
        int idx = tid + it * 256;          // 4096 = 128 rows x 32 float4
        int r = idx >> 5, c4 = (idx & 31) << 2;
        uint32_t soff = (uint32_t)r * ROWB + (uint32_t)c4 * 2;

        float4 v = *reinterpret_cast<const float4*>(A + (size_t)(mBase + r) * 128 + c4);
        uint32_t h0, l0, h1, l1;
        split2(v.x, v.y, h0, l0);
        split2(v.z, v.w, h1, l1);
        *reinterpret_cast<uint2*>(sm + SM_AHI + soff) = make_uint2(h0, h1);
        *reinterpret_cast<uint2*>(sm + SM_ALO + soff) = make_uint2(l0, l1);

        int n = nBase + r;
        float4 w = make_float4(0.f, 0.f, 0.f, 0.f);
        if (n < N) w = *reinterpret_cast<const float4*>(B + (size_t)n * 128 + c4);
        split2(w.x, w.y, h0, l0);
        split2(w.z, w.w, h1, l1);
        *reinterpret_cast<uint2*>(sm + SM_BHI + soff) = make_uint2(h0, h1);
        *reinterpret_cast<uint2*>(sm + SM_BLO + soff) = make_uint2(l0, l1);
    }
    __syncthreads();

    // ---- warp tiling: 2 (M) x 4 (N) warps; each warp 64x32 ----
    const int wm = wid >> 2, wn = wid & 3;

    float acc[4][4][4];
    #pragma unroll
    for (int mf = 0; mf < 4; ++mf)
        #pragma unroll
        for (int nf = 0; nf < 4; ++nf)
            #pragma unroll
            for (int e = 0; e < 4; ++e) acc[mf][nf][e] = 0.f;

    const char* aH = sm + SM_AHI + (uint32_t)(wm * 64 + g) * ROWB + tig * 4;
    const char* aL = sm + SM_ALO + (uint32_t)(wm * 64 + g) * ROWB + tig * 4;
    const char* bH = sm + SM_BHI + (uint32_t)(wn * 32 + g) * ROWB + tig * 4;
    const char* bL = sm + SM_BLO + (uint32_t)(wn * 32 + g) * ROWB + tig * 4;

    #pragma unroll
    for (int ks = 0; ks < 8; ++ks) {
        const int kb = ks * 32;            // 16 cols * 2B per k-step

        uint32_t ah[4][4], bh[4][2];
        #pragma unroll
        for (int mf = 0; mf < 4; ++mf) {
            const char* p = aH + mf * (16 * ROWB) + kb;
            ah[mf][0] = *reinterpret_cast<const uint32_t*>(p);
            ah[mf][1] = *reinterpret_cast<const uint32_t*>(p + 8 * ROWB);
            ah[mf][2] = *reinterpret_cast<const uint32_t*>(p + 16);
            ah[mf][3] = *reinterpret_cast<const uint32_t*>(p + 8 * ROWB + 16);
        }
        #pragma unroll
        for (int nf = 0; nf < 4; ++nf) {
            const char* p = bH + nf * (8 * ROWB) + kb;
            bh[nf][0] = *reinterpret_cast<const uint32_t*>(p);
            bh[nf][1] = *reinterpret_cast<const uint32_t*>(p + 16);
        }
        #pragma unroll
        for (int mf = 0; mf < 4; ++mf)
            #pragma unroll
            for (int nf = 0; nf < 4; ++nf)
                MMA_BF16(acc[mf][nf], ah[mf], bh[nf]);       // hi * hi

        uint32_t bl[4][2];
        #pragma unroll
        for (int nf = 0; nf < 4; ++nf) {
            const char* p = bL + nf * (8 * ROWB) + kb;
            bl[nf][0] = *reinterpret_cast<const uint32_t*>(p);
            bl[nf][1] = *reinterpret_cast<const uint32_t*>(p + 16);
        }
        #pragma unroll
        for (int mf = 0; mf < 4; ++mf)
            #pragma unroll
            for (int nf = 0; nf < 4; ++nf)
                MMA_BF16(acc[mf][nf], ah[mf], bl[nf]);       // hi * lo

        uint32_t al[4][4];
        #pragma unroll
        for (int mf = 0; mf < 4; ++mf) {
            const char* p = aL + mf * (16 * ROWB) + kb;
            al[mf][0] = *reinterpret_cast<const uint32_t*>(p);
            al[mf][1] = *reinterpret_cast<const uint32_t*>(p + 8 * ROWB);
            al[mf][2] = *reinterpret_cast<const uint32_t*>(p + 16);
            al[mf][3] = *reinterpret_cast<const uint32_t*>(p + 8 * ROWB + 16);
        }
        #pragma unroll
        for (int mf = 0; mf < 4; ++mf)
            #pragma unroll
            for (int nf = 0; nf < 4; ++nf)
                MMA_BF16(acc[mf][nf], al[mf], bh[nf]);       // lo * hi
    }

    // ---- epilogue: C fragments -> gmem (4 lanes x 2 floats = 32B sectors) ----
    #pragma unroll
    for (int mf = 0; mf < 4; ++mf) {
        int row0 = mBase + wm * 64 + mf * 16 + g;
        #pragma unroll
        for (int nf = 0; nf < 4; ++nf) {
            int col = nBase + wn * 32 + nf * 8 + tig * 2;
            if (col < N) {
                C[(size_t)row0 * N + col]       = acc[mf][nf][0];
                C[(size_t)(row0 + 8) * N + col] = acc[mf][nf][2];
                if (col + 1 < N) {
                    C[(size_t)row0 * N + col + 1]       = acc[mf][nf][1];
                    C[(size_t)(row0 + 8) * N + col + 1] = acc[mf][nf][3];
                }
            }
        }
    }
}

// ---------------- small kernels (unchanged) ----------------
__global__ void prep_kernel(const float* __restrict__ ggnn) {
    int idx = blockIdx.x * 256 + threadIdx.x;
    if (idx < NTOT * HDIM) g_agg[idx] = 0.f;
    if (idx < HDIM * HDIM) {
        int k = idx >> 7, h = idx & 127;
        g_gT[h * HDIM + k] = ggnn[idx];
    }
}

__global__ void gather_kernel(const int* __restrict__ items,
                              const float* __restrict__ emb) {
    int idx = blockIdx.x * 256 + threadIdx.x;
    int node = idx >> 7, h = idx & 127;
    g_x[idx] = emb[(size_t)items[node] * HDIM + h];
}

__global__ void scatter_kernel(const int* __restrict__ ei) {
    int e = blockIdx.x;
    int h = threadIdx.x;
    int s = ei[e], d = ei[NEDGE + e];
    atomicAdd(&g_agg[(size_t)d * HDIM + h], g_m[(size_t)s * HDIM + h]);
}

__global__ void gru_kernel(const float* __restrict__ b_ih,
                           const float* __restrict__ b_hh) {
    int idx = blockIdx.x * 256 + threadIdx.x;
    int node = idx >> 7, h = idx & 127;
    const float* gi = g_gi + (size_t)node * 384;
    const float* gh = g_gh + (size_t)node * 384;
    float ir = gi[h]       + b_ih[h],       hr = gh[h]       + b_hh[h];
    float iz = gi[128 + h] + b_ih[128 + h], hz = gh[128 + h] + b_hh[128 + h];
    float in_= gi[256 + h] + b_ih[256 + h], hn = gh[256 + h] + b_hh[256 + h];
    float r = 1.f / (1.f + expf(-(ir + hr)));
    float z = 1.f / (1.f + expf(-(iz + hz)));
    float n = tanhf(in_ + r * hn);
    g_x[idx] = (1.f - z) * n + z * g_x[idx];
}

__global__ void hidden_kernel(const int* __restrict__ items,
                              const int* __restrict__ seq,
                              const int* __restrict__ mask,
                              const float* __restrict__ emb) {
    int b = blockIdx.x, h = threadIdx.x;
    __shared__ int it_s[NNODE];
    __shared__ int sl;
    if (h < NNODE) it_s[h] = items[b * NNODE + h];
    if (h == 0) {
        int c = 0;
        for (int l = 0; l < SEQL; ++l) c += mask[b * SEQL + l];
        sl = c - 1;
    }
    __syncthreads();
    int seqlen = sl;
    for (int l = 0; l < SEQL; ++l) {
        int s = seq[b * SEQL + l];
        float v = 0.f;
        if (s != 0) {
            int found = -1;
            #pragma unroll
            for (int ns = 0; ns < NNODE; ++ns)
                if (found < 0 && it_s[ns] == s) found = ns;
            v = (found >= 0) ? g_x[(size_t)(b * NNODE + found) * HDIM + h]
                             : emb[(size_t)s * HDIM + h];
        }
        g_hidden[(size_t)(b * SEQL + l) * HDIM + h] = v;
        if (l == seqlen) g_ht[b * HDIM + h] = v;
    }
}

__device__ __forceinline__ float blockSum128(float v, float* red) {
    #pragma unroll
    for (int o = 16; o > 0; o >>= 1) v += __shfl_xor_sync(0xffffffffu, v, o);
    if ((threadIdx.x & 31) == 0) red[threadIdx.x >> 5] = v;
    __syncthreads();
    v = red[0] + red[1] + red[2] + red[3];
    __syncthreads();
    return v;
}

__global__ void attn_kernel(const int* __restrict__ mask,
                            const float* __restrict__ b1,
                            const float* __restrict__ b2,
                            const float* __restrict__ w3,
                            const float* __restrict__ Wt,
                            const float* __restrict__ bt,
                            const float* __restrict__ gamma,
                            const float* __restrict__ beta) {
    int b = blockIdx.x, h = threadIdx.x;
    __shared__ float hid[SEQL * HDIM];
    __shared__ float red[4];
    __shared__ float a_s[HDIM], ht_s[HDIM];
    __shared__ int msk[SEQL];
    for (int i = h; i < SEQL * HDIM; i += 128) hid[i] = g_hidden[(size_t)b * SEQL * HDIM + i];
    if (h < SEQL) msk[h] = mask[b * SEQL + h];
    __syncthreads();

    float q1v = g_q1[b * HDIM + h] + b1[h];
    float b2v = b2[h];
    float w3v = w3[h];
    float acc = 0.f;
    for (int l = 0; l < SEQL; ++l) {
        float q2v = g_q2[(size_t)(b * SEQL + l) * HDIM + h] + b2v;
        float s = 1.f / (1.f + expf(-(q1v + q2v)));
        float alpha = blockSum128(s * w3v, red);
        if (msk[l]) acc += alpha * hid[l * HDIM + h];
    }
    int seqlen = -1;
    #pragma unroll
    for (int l = 0; l < SEQL; ++l) seqlen += msk[l];

    a_s[h]  = acc;
    ht_s[h] = hid[seqlen * HDIM + h];
    __syncthreads();

    float av = bt[h];
    const float* wr = Wt + (size_t)h * 256;
    #pragma unroll 8
    for (int k = 0; k < HDIM; ++k) av += a_s[k]  * wr[k];
    #pragma unroll 8
    for (int k = 0; k < HDIM; ++k) av += ht_s[k] * wr[HDIM + k];

    float mu  = blockSum128(av, red) * (1.f / HDIM);
    float d   = av - mu;
    float var = blockSum128(d * d, red) * (1.f / HDIM);
    g_afin[b * HDIM + h] = d * rsqrtf(var + 1e-5f) * gamma[h] + beta[h];
}

// ---------------- launch ----------------
extern "C" void kernel_launch(void* const* d_in, const int* in_sizes, int n_in,
                              void* d_out, int out_size) {
    const int*   items = (const int*)  d_in[0];
    const int*   eidx  = (const int*)  d_in[1];
    const int*   seq   = (const int*)  d_in[2];
    const int*   mask  = (const int*)  d_in[3];
    const float* emb   = (const float*)d_in[4];
    const float* ggnn  = (const float*)d_in[5];
    const float* Wih   = (const float*)d_in[6];
    const float* Whh   = (const float*)d_in[7];
    const float* bih   = (const float*)d_in[8];
    const float* bhh   = (const float*)d_in[9];
    const float* W1    = (const float*)d_in[10];
    const float* b1    = (const float*)d_in[11];
    const float* W2    = (const float*)d_in[12];
    const float* b2    = (const float*)d_in[13];
    const float* w3    = (const float*)d_in[14];
    const float* Wt    = (const float*)d_in[15];
    const float* bt    = (const float*)d_in[16];
    const float* gamma = (const float*)d_in[17];
    const float* beta  = (const float*)d_in[18];
    float* out = (float*)d_out;

    float *px, *pm, *pagg, *pgi, *pgh, *pgT, *phid, *pht, *pq1, *pq2, *pafin;
    cudaGetSymbolAddress((void**)&px,    g_x);
    cudaGetSymbolAddress((void**)&pm,    g_m);
    cudaGetSymbolAddress((void**)&pagg,  g_agg);
    cudaGetSymbolAddress((void**)&pgi,   g_gi);
    cudaGetSymbolAddress((void**)&pgh,   g_gh);
    cudaGetSymbolAddress((void**)&pgT,   g_gT);
    cudaGetSymbolAddress((void**)&phid,  g_hidden);
    cudaGetSymbolAddress((void**)&pht,   g_ht);
    cudaGetSymbolAddress((void**)&pq1,   g_q1);
    cudaGetSymbolAddress((void**)&pq2,   g_q2);
    cudaGetSymbolAddress((void**)&pafin, g_afin);

    cudaFuncSetAttribute(gemm_tc, cudaFuncAttributeMaxDynamicSharedMemorySize, SM_TOTAL);

    prep_kernel  <<<4096, 256>>>(ggnn);
    gather_kernel<<<4096, 256>>>(items, emb);
    gemm_tc<<<dim3(1, 64),  256, SM_TOTAL>>>(px,   pgT, pm,  HDIM);     // m = x @ ggnn_w
    scatter_kernel<<<NEDGE, 128>>>(eidx);
    gemm_tc<<<dim3(3, 64),  256, SM_TOTAL>>>(pagg, Wih, pgi, 3*HDIM);   // gi
    gemm_tc<<<dim3(3, 64),  256, SM_TOTAL>>>(px,   Whh, pgh, 3*HDIM);   // gh
    gru_kernel   <<<4096, 256>>>(bih, bhh);
    hidden_kernel<<<BATCH, 128>>>(items, seq, mask, emb);
    gemm_tc<<<dim3(1, 4),   256, SM_TOTAL>>>(pht,  W1,  pq1, HDIM);     // q1
    gemm_tc<<<dim3(1, 80),  256, SM_TOTAL>>>(phid, W2,  pq2, HDIM);     // q2
    attn_kernel  <<<BATCH, 128>>>(mask, b1, b2, w3, Wt, bt, gamma, beta);
    gemm_tc<<<dim3((NOUT + 127)/128, 4), 256, SM_TOTAL>>>(pafin, emb + HDIM, out, NOUT);
}

// round 10
// speedup vs baseline: 2.0425x; 1.0291x over previous
#include <cuda_runtime.h>
#include <cuda_bf16.h>
#include <math.h>
#include <cstdint>

// ---------------- problem constants ----------------
#define BATCH 512
#define SEQL  20
#define NNODE 16
#define EPS_  32
#define HDIM  128
#define VOCAB 100000
#define NTOT  (BATCH*NNODE)        // 8192
#define NEDGE (BATCH*EPS_)         // 16384
#define NOUT  (VOCAB-1)            // 99999
#define NT_   782                  // ceil(NOUT/128)
#define NJOBS (4*NT_)              // 3128
#define PGRID 148

// ---------------- device scratch (no allocs allowed) ----------------
__device__ float g_x[NTOT*HDIM];
__device__ float g_m[NTOT*HDIM];
__device__ float g_agg[NTOT*HDIM];
__device__ float g_gi[NTOT*3*HDIM];
__device__ float g_gh[NTOT*3*HDIM];
__device__ float g_gT[HDIM*HDIM];
__device__ float g_hidden[BATCH*SEQL*HDIM];
__device__ float g_ht[BATCH*HDIM];
__device__ float g_q1[BATCH*HDIM];
__device__ float g_q2[BATCH*SEQL*HDIM];
__device__ float g_afin[BATCH*HDIM];

// ---------------- split-bf16 tensor-core GEMM pieces ----------------
// smem tiles: bf16 [128 rows][128 cols], rows padded to 272B (136 bf16):
// bank(row,tig) = (4*row + tig) mod 32 -> conflict-free fragment loads.
#define ROWB     272
#define SM_AHI   0
#define SM_ALO   34816
#define SM_BHI   69632
#define SM_BLO   104448
#define SM_TOTAL 139264
// persistent kernel adds a 64KB fp32 staging buffer
#define SM_STAGE 139264
#define SM_PTOT  (139264 + 65536)

__device__ __forceinline__ uint32_t smem_to_u32(const void* p) {
    uint32_t a;
    asm("{ .reg .u64 t; cvta.to.shared.u64 t, %1; cvt.u32.u64 %0, t; }" : "=r"(a) : "l"(p));
    return a;
}

// hi = bf16 bits via truncation (exact split: lo = x - hi representable in fp32)
__device__ __forceinline__ void split2(float x, float y, uint32_t& hi, uint32_t& lo) {
    uint32_t ux = __float_as_uint(x), uy = __float_as_uint(y);
    hi = __byte_perm(ux, uy, 0x7632);                    // {x.hi16, y.hi16}
    float lx = x - __uint_as_float(ux & 0xffff0000u);
    float ly = y - __uint_as_float(uy & 0xffff0000u);
    __nv_bfloat162 t = __floats2bfloat162_rn(lx, ly);
    lo = *reinterpret_cast<uint32_t*>(&t);
}

#define MMA_BF16(d, a, b)                                                        \
    asm volatile("mma.sync.aligned.m16n8k16.row.col.f32.bf16.bf16.f32 "         \
                 "{%0,%1,%2,%3}, {%4,%5,%6,%7}, {%8,%9}, {%0,%1,%2,%3};"        \
                 : "+f"((d)[0]), "+f"((d)[1]), "+f"((d)[2]), "+f"((d)[3])        \
                 : "r"((a)[0]), "r"((a)[1]), "r"((a)[2]), "r"((a)[3]),           \
                   "r"((b)[0]), "r"((b)[1]))

#define CP_ASYNC16(daddr, gptr) \
    asm volatile("cp.async.cg.shared.global [%0], [%1], 16;" :: "r"(daddr), "l"(gptr))
#define CP_COMMIT() asm volatile("cp.async.commit_group;" ::: "memory")
#define CP_WAIT0()  asm volatile("cp.async.wait_group 0;"  ::: "memory")

// issue cp.async of a [128 x 128] fp32 tile (rows rowBase..) into staging
__device__ __forceinline__ void load_tile_async(
    const float* __restrict__ src, int rowBase, int maxRow,
    uint32_t stage_u32, char* sm, int tid)
{
    #pragma unroll
    for (int it = 0; it < 16; ++it) {
        int idx = tid + it * 256;
        int r = idx >> 5, c4 = (idx & 31) << 2;
        uint32_t daddr = stage_u32 + (uint32_t)idx * 16;
        int row = rowBase + r;
        if (row < maxRow) {
            CP_ASYNC16(daddr, src + (size_t)row * 128 + c4);
        } else {
            *reinterpret_cast<float4*>(sm + SM_STAGE + (size_t)idx * 16) =
                make_float4(0.f, 0.f, 0.f, 0.f);
        }
    }
}

// convert fp32 staging tile -> bf16 hi/lo padded tiles
__device__ __forceinline__ void convert_tile(
    const float4* __restrict__ stage, char* sm, int dhi, int dlo, int tid)
{
    #pragma unroll
    for (int it = 0; it < 16; ++it) {
        int idx = tid + it * 256;
        int r = idx >> 5, c4 = (idx & 31) << 2;
        uint32_t soff = (uint32_t)r * ROWB + (uint32_t)c4 * 2;
        float4 v = stage[idx];
        uint32_t h0, l0, h1, l1;
        split2(v.x, v.y, h0, l0);
        split2(v.z, v.w, h1, l1);
        *reinterpret_cast<uint2*>(sm + dhi + soff) = make_uint2(h0, h1);
        *reinterpret_cast<uint2*>(sm + dlo + soff) = make_uint2(l0, l1);
    }
}

// ---------------- generic one-tile GEMM (for the small layers) ----------------
__global__ __launch_bounds__(256) void gemm_tc(
    const float* __restrict__ A, const float* __restrict__ B,
    float* __restrict__ C, int N)
{
    extern __shared__ char sm[];
    const int tid  = threadIdx.x, wid = tid >> 5, lane = tid & 31;
    const int g    = lane >> 2, tig = lane & 3;
    const int mBase = blockIdx.y << 7, nBase = blockIdx.x << 7;

    #pragma unroll
    for (int it = 0; it < 16; ++it) {
        int idx = tid + it * 256;
        int r = idx >> 5, c4 = (idx & 31) << 2;
        uint32_t soff = (uint32_t)r * ROWB + (uint32_t)c4 * 2;

        float4 v = *reinterpret_cast<const float4*>(A + (size_t)(mBase + r) * 128 + c4);
        uint32_t h0, l0, h1, l1;
        split2(v.x, v.y, h0, l0);
        split2(v.z, v.w, h1, l1);
        *reinterpret_cast<uint2*>(sm + SM_AHI + soff) = make_uint2(h0, h1);
        *reinterpret_cast<uint2*>(sm + SM_ALO + soff) = make_uint2(l0, l1);

        int n = nBase + r;
        float4 w = make_float4(0.f, 0.f, 0.f, 0.f);
        if (n < N) w = *reinterpret_cast<const float4*>(B + (size_t)n * 128 + c4);
        split2(w.x, w.y, h0, l0);
        split2(w.z, w.w, h1, l1);
        *reinterpret_cast<uint2*>(sm + SM_BHI + soff) = make_uint2(h0, h1);
        *reinterpret_cast<uint2*>(sm + SM_BLO + soff) = make_uint2(l0, l1);
    }
    __syncthreads();

    const int wm = wid >> 2, wn = wid & 3;

    float acc[4][4][4];
    #pragma unroll
    for (int mf = 0; mf < 4; ++mf)
        #pragma unroll
        for (int nf = 0; nf < 4; ++nf)
            #pragma unroll
            for (int e = 0; e < 4; ++e) acc[mf][nf][e] = 0.f;

    const char* aH = sm + SM_AHI + (uint32_t)(wm * 64 + g) * ROWB + tig * 4;
    const char* aL = sm + SM_ALO + (uint32_t)(wm * 64 + g) * ROWB + tig * 4;
    const char* bH = sm + SM_BHI + (uint32_t)(wn * 32 + g) * ROWB + tig * 4;
    const char* bL = sm + SM_BLO + (uint32_t)(wn * 32 + g) * ROWB + tig * 4;

    #pragma unroll
    for (int ks = 0; ks < 8; ++ks) {
        const int kb = ks * 32;
        uint32_t ah[4][4], bh[4][2];
        #pragma unroll
        for (int mf = 0; mf < 4; ++mf) {
            const char* p = aH + mf * (16 * ROWB) + kb;
            ah[mf][0] = *reinterpret_cast<const uint32_t*>(p);
            ah[mf][1] = *reinterpret_cast<const uint32_t*>(p + 8 * ROWB);
            ah[mf][2] = *reinterpret_cast<const uint32_t*>(p + 16);
            ah[mf][3] = *reinterpret_cast<const uint32_t*>(p + 8 * ROWB + 16);
        }
        #pragma unroll
        for (int nf = 0; nf < 4; ++nf) {
            const char* p = bH + nf * (8 * ROWB) + kb;
            bh[nf][0] = *reinterpret_cast<const uint32_t*>(p);
            bh[nf][1] = *reinterpret_cast<const uint32_t*>(p + 16);
        }
        #pragma unroll
        for (int mf = 0; mf < 4; ++mf)
            #pragma unroll
            for (int nf = 0; nf < 4; ++nf)
                MMA_BF16(acc[mf][nf], ah[mf], bh[nf]);

        uint32_t bl[4][2];
        #pragma unroll
        for (int nf = 0; nf < 4; ++nf) {
            const char* p = bL + nf * (8 * ROWB) + kb;
            bl[nf][0] = *reinterpret_cast<const uint32_t*>(p);
            bl[nf][1] = *reinterpret_cast<const uint32_t*>(p + 16);
        }
        #pragma unroll
        for (int mf = 0; mf < 4; ++mf)
            #pragma unroll
            for (int nf = 0; nf < 4; ++nf)
                MMA_BF16(acc[mf][nf], ah[mf], bl[nf]);

        uint32_t al[4][4];
        #pragma unroll
        for (int mf = 0; mf < 4; ++mf) {
            const char* p = aL + mf * (16 * ROWB) + kb;
            al[mf][0] = *reinterpret_cast<const uint32_t*>(p);
            al[mf][1] = *reinterpret_cast<const uint32_t*>(p + 8 * ROWB);
            al[mf][2] = *reinterpret_cast<const uint32_t*>(p + 16);
            al[mf][3] = *reinterpret_cast<const uint32_t*>(p + 8 * ROWB + 16);
        }
        #pragma unroll
        for (int mf = 0; mf < 4; ++mf)
            #pragma unroll
            for (int nf = 0; nf < 4; ++nf)
                MMA_BF16(acc[mf][nf], al[mf], bh[nf]);
    }

    #pragma unroll
    for (int mf = 0; mf < 4; ++mf) {
        int row0 = mBase + wm * 64 + mf * 16 + g;
        #pragma unroll
        for (int nf = 0; nf < 4; ++nf) {
            int col = nBase + wn * 32 + nf * 8 + tig * 2;
            if (col < N) {
                C[(size_t)row0 * N + col]       = acc[mf][nf][0];
                C[(size_t)(row0 + 8) * N + col] = acc[mf][nf][2];
                if (col + 1 < N) {
                    C[(size_t)row0 * N + col + 1]       = acc[mf][nf][1];
                    C[(size_t)(row0 + 8) * N + col + 1] = acc[mf][nf][3];
                }
            }
        }
    }
}

// ---------------- persistent vocab GEMM: C[512, NOUT] = afin * emb[1:]^T ----------------
__global__ __launch_bounds__(256) void gemm_scores(
    const float* __restrict__ A, const float* __restrict__ B,
    float* __restrict__ C)
{
    extern __shared__ char sm[];
    uint32_t smb = smem_to_u32(sm);
    uint32_t stage_u32 = smb + SM_STAGE;
    const float4* stage = reinterpret_cast<const float4*>(sm + SM_STAGE);

    const int tid  = threadIdx.x, wid = tid >> 5, lane = tid & 31;
    const int g    = lane >> 2, tig = lane & 3;
    const int wm   = wid >> 2, wn = wid & 3;

    const char* aH = sm + SM_AHI + (uint32_t)(wm * 64 + g) * ROWB + tig * 4;
    const char* aL = sm + SM_ALO + (uint32_t)(wm * 64 + g) * ROWB + tig * 4;
    const char* bH = sm + SM_BHI + (uint32_t)(wn * 32 + g) * ROWB + tig * 4;
    const char* bL = sm + SM_BLO + (uint32_t)(wn * 32 + g) * ROWB + tig * 4;

    int  m_cur = -1;
    bool pf = false;

    for (int j = blockIdx.x; j < NJOBS; j += PGRID) {
        const int m = j / NT_;
        const int n = j - m * NT_;

        if (m != m_cur) {
            // load + convert A tile (rare: <= 3x per CTA). staging is idle here.
            load_tile_async(A, m << 7, BATCH, stage_u32, sm, tid);
            CP_COMMIT();
            CP_WAIT0();
            __syncthreads();                    // staging ready; prior compute done
            convert_tile(stage, sm, SM_AHI, SM_ALO, tid);
            __syncthreads();                    // Ah/Al ready; staging reads done
            m_cur = m;
            pf = false;
        }
        if (!pf) {                               // first job of a segment
            load_tile_async(B, n << 7, NOUT, stage_u32, sm, tid);
            CP_COMMIT();
        }
        CP_WAIT0();
        __syncthreads();                         // staging ready + Bh/Bl free
        convert_tile(stage, sm, SM_BHI, SM_BLO, tid);
        __syncthreads();                         // Bh/Bl ready; staging reads done

        // prefetch next job's B into staging; lands during the MMA phase below
        const int jn = j + PGRID;
        if (jn < NJOBS && (jn / NT_) == m_cur) {
            load_tile_async(B, (jn - m_cur * NT_) << 7, NOUT, stage_u32, sm, tid);
            CP_COMMIT();
            pf = true;
        } else {
            pf = false;
        }

        // ---- MMA phase ----
        float acc[4][4][4];
        #pragma unroll
        for (int mf = 0; mf < 4; ++mf)
            #pragma unroll
            for (int nf = 0; nf < 4; ++nf)
                #pragma unroll
                for (int e = 0; e < 4; ++e) acc[mf][nf][e] = 0.f;

        #pragma unroll
        for (int ks = 0; ks < 8; ++ks) {
            const int kb = ks * 32;
            uint32_t ah[4][4], bh[4][2];
            #pragma unroll
            for (int mf = 0; mf < 4; ++mf) {
                const char* p = aH + mf * (16 * ROWB) + kb;
                ah[mf][0] = *reinterpret_cast<const uint32_t*>(p);
                ah[mf][1] = *reinterpret_cast<const uint32_t*>(p + 8 * ROWB);
                ah[mf][2] = *reinterpret_cast<const uint32_t*>(p + 16);
                ah[mf][3] = *reinterpret_cast<const uint32_t*>(p + 8 * ROWB + 16);
            }
            #pragma unroll
            for (int nf = 0; nf < 4; ++nf) {
                const char* p = bH + nf * (8 * ROWB) + kb;
                bh[nf][0] = *reinterpret_cast<const uint32_t*>(p);
                bh[nf][1] = *reinterpret_cast<const uint32_t*>(p + 16);
            }
            #pragma unroll
            for (int mf = 0; mf < 4; ++mf)
                #pragma unroll
                for (int nf = 0; nf < 4; ++nf)
                    MMA_BF16(acc[mf][nf], ah[mf], bh[nf]);

            uint32_t bl[4][2];
            #pragma unroll
            for (int nf = 0; nf < 4; ++nf) {
                const char* p = bL + nf * (8 * ROWB) + kb;
                bl[nf][0] = *reinterpret_cast<const uint32_t*>(p);
                bl[nf][1] = *reinterpret_cast<const uint32_t*>(p + 16);
            }
            #pragma unroll
            for (int mf = 0; mf < 4; ++mf)
                #pragma unroll
                for (int nf = 0; nf < 4; ++nf)
                    MMA_BF16(acc[mf][nf], ah[mf], bl[nf]);

            uint32_t al[4][4];
            #pragma unroll
            for (int mf = 0; mf < 4; ++mf) {
                const char* p = aL + mf * (16 * ROWB) + kb;
                al[mf][0] = *reinterpret_cast<const uint32_t*>(p);
                al[mf][1] = *reinterpret_cast<const uint32_t*>(p + 8 * ROWB);
                al[mf][2] = *reinterpret_cast<const uint32_t*>(p + 16);
                al[mf][3] = *reinterpret_cast<const uint32_t*>(p + 8 * ROWB + 16);
            }
            #pragma unroll
            for (int mf = 0; mf < 4; ++mf)
                #pragma unroll
                for (int nf = 0; nf < 4; ++nf)
                    MMA_BF16(acc[mf][nf], al[mf], bh[nf]);
        }

        // ---- epilogue ----
        const int mBase = m_cur << 7, nBase = n << 7;
        #pragma unroll
        for (int mf = 0; mf < 4; ++mf) {
            int row0 = mBase + wm * 64 + mf * 16 + g;
            #pragma unroll
            for (int nf = 0; nf < 4; ++nf) {
                int col = nBase + wn * 32 + nf * 8 + tig * 2;
                if (col < NOUT) {
                    C[(size_t)row0 * NOUT + col]       = acc[mf][nf][0];
                    C[(size_t)(row0 + 8) * NOUT + col] = acc[mf][nf][2];
                    if (col + 1 < NOUT) {
                        C[(size_t)row0 * NOUT + col + 1]       = acc[mf][nf][1];
                        C[(size_t)(row0 + 8) * NOUT + col + 1] = acc[mf][nf][3];
                    }
                }
            }
        }
        // next iteration's CP_WAIT0 + __syncthreads protects Bh/Bl overwrite
    }
}

// ---------------- small kernels (unchanged) ----------------
__global__ void prep_kernel(const float* __restrict__ ggnn) {
    int idx = blockIdx.x * 256 + threadIdx.x;
    if (idx < NTOT * HDIM) g_agg[idx] = 0.f;
    if (idx < HDIM * HDIM) {
        int k = idx >> 7, h = idx & 127;
        g_gT[h * HDIM + k] = ggnn[idx];
    }
}

__global__ void gather_kernel(const int* __restrict__ items,
                              const float* __restrict__ emb) {
    int idx = blockIdx.x * 256 + threadIdx.x;
    int node = idx >> 7, h = idx & 127;
    g_x[idx] = emb[(size_t)items[node] * HDIM + h];
}

__global__ void scatter_kernel(const int* __restrict__ ei) {
    int e = blockIdx.x;
    int h = threadIdx.x;
    int s = ei[e], d = ei[NEDGE + e];
    atomicAdd(&g_agg[(size_t)d * HDIM + h], g_m[(size_t)s * HDIM + h]);
}

__global__ void gru_kernel(const float* __restrict__ b_ih,
                           const float* __restrict__ b_hh) {
    int idx = blockIdx.x * 256 + threadIdx.x;
    int node = idx >> 7, h = idx & 127;
    const float* gi = g_gi + (size_t)node * 384;
    const float* gh = g_gh + (size_t)node * 384;
    float ir = gi[h]       + b_ih[h],       hr = gh[h]       + b_hh[h];
    float iz = gi[128 + h] + b_ih[128 + h], hz = gh[128 + h] + b_hh[128 + h];
    float in_= gi[256 + h] + b_ih[256 + h], hn = gh[256 + h] + b_hh[256 + h];
    float r = 1.f / (1.f + expf(-(ir + hr)));
    float z = 1.f / (1.f + expf(-(iz + hz)));
    float n = tanhf(in_ + r * hn);
    g_x[idx] = (1.f - z) * n + z * g_x[idx];
}

__global__ void hidden_kernel(const int* __restrict__ items,
                              const int* __restrict__ seq,
                              const int* __restrict__ mask,
                              const float* __restrict__ emb) {
    int b = blockIdx.x, h = threadIdx.x;
    __shared__ int it_s[NNODE];
    __shared__ int sl;
    if (h < NNODE) it_s[h] = items[b * NNODE + h];
    if (h == 0) {
        int c = 0;
        for (int l = 0; l < SEQL; ++l) c += mask[b * SEQL + l];
        sl = c - 1;
    }
    __syncthreads();
    int seqlen = sl;
    for (int l = 0; l < SEQL; ++l) {
        int s = seq[b * SEQL + l];
        float v = 0.f;
        if (s != 0) {
            int found = -1;
            #pragma unroll
            for (int ns = 0; ns < NNODE; ++ns)
                if (found < 0 && it_s[ns] == s) found = ns;
            v = (found >= 0) ? g_x[(size_t)(b * NNODE + found) * HDIM + h]
                             : emb[(size_t)s * HDIM + h];
        }
        g_hidden[(size_t)(b * SEQL + l) * HDIM + h] = v;
        if (l == seqlen) g_ht[b * HDIM + h] = v;
    }
}

__device__ __forceinline__ float blockSum128(float v, float* red) {
    #pragma unroll
    for (int o = 16; o > 0; o >>= 1) v += __shfl_xor_sync(0xffffffffu, v, o);
    if ((threadIdx.x & 31) == 0) red[threadIdx.x >> 5] = v;
    __syncthreads();
    v = red[0] + red[1] + red[2] + red[3];
    __syncthreads();
    return v;
}

__global__ void attn_kernel(const int* __restrict__ mask,
                            const float* __restrict__ b1,
                            const float* __restrict__ b2,
                            const float* __restrict__ w3,
                            const float* __restrict__ Wt,
                            const float* __restrict__ bt,
                            const float* __restrict__ gamma,
                            const float* __restrict__ beta) {
    int b = blockIdx.x, h = threadIdx.x;
    __shared__ float hid[SEQL * HDIM];
    __shared__ float red[4];
    __shared__ float a_s[HDIM], ht_s[HDIM];
    __shared__ int msk[SEQL];
    for (int i = h; i < SEQL * HDIM; i += 128) hid[i] = g_hidden[(size_t)b * SEQL * HDIM + i];
    if (h < SEQL) msk[h] = mask[b * SEQL + h];
    __syncthreads();

    float q1v = g_q1[b * HDIM + h] + b1[h];
    float b2v = b2[h];
    float w3v = w3[h];
    float acc = 0.f;
    for (int l = 0; l < SEQL; ++l) {
        float q2v = g_q2[(size_t)(b * SEQL + l) * HDIM + h] + b2v;
        float s = 1.f / (1.f + expf(-(q1v + q2v)));
        float alpha = blockSum128(s * w3v, red);
        if (msk[l]) acc += alpha * hid[l * HDIM + h];
    }
    int seqlen = -1;
    #pragma unroll
    for (int l = 0; l < SEQL; ++l) seqlen += msk[l];

    a_s[h]  = acc;
    ht_s[h] = hid[seqlen * HDIM + h];
    __syncthreads();

    float av = bt[h];
    const float* wr = Wt + (size_t)h * 256;
    #pragma unroll 8
    for (int k = 0; k < HDIM; ++k) av += a_s[k]  * wr[k];
    #pragma unroll 8
    for (int k = 0; k < HDIM; ++k) av += ht_s[k] * wr[HDIM + k];

    float mu  = blockSum128(av, red) * (1.f / HDIM);
    float d   = av - mu;
    float var = blockSum128(d * d, red) * (1.f / HDIM);
    g_afin[b * HDIM + h] = d * rsqrtf(var + 1e-5f) * gamma[h] + beta[h];
}

// ---------------- launch ----------------
extern "C" void kernel_launch(void* const* d_in, const int* in_sizes, int n_in,
                              void* d_out, int out_size) {
    const int*   items = (const int*)  d_in[0];
    const int*   eidx  = (const int*)  d_in[1];
    const int*   seq   = (const int*)  d_in[2];
    const int*   mask  = (const int*)  d_in[3];
    const float* emb   = (const float*)d_in[4];
    const float* ggnn  = (const float*)d_in[5];
    const float* Wih   = (const float*)d_in[6];
    const float* Whh   = (const float*)d_in[7];
    const float* bih   = (const float*)d_in[8];
    const float* bhh   = (const float*)d_in[9];
    const float* W1    = (const float*)d_in[10];
    const float* b1    = (const float*)d_in[11];
    const float* W2    = (const float*)d_in[12];
    const float* b2    = (const float*)d_in[13];
    const float* w3    = (const float*)d_in[14];
    const float* Wt    = (const float*)d_in[15];
    const float* bt    = (const float*)d_in[16];
    const float* gamma = (const float*)d_in[17];
    const float* beta  = (const float*)d_in[18];
    float* out = (float*)d_out;

    float *px, *pm, *pagg, *pgi, *pgh, *pgT, *phid, *pht, *pq1, *pq2, *pafin;
    cudaGetSymbolAddress((void**)&px,    g_x);
    cudaGetSymbolAddress((void**)&pm,    g_m);
    cudaGetSymbolAddress((void**)&pagg,  g_agg);
    cudaGetSymbolAddress((void**)&pgi,   g_gi);
    cudaGetSymbolAddress((void**)&pgh,   g_gh);
    cudaGetSymbolAddress((void**)&pgT,   g_gT);
    cudaGetSymbolAddress((void**)&phid,  g_hidden);
    cudaGetSymbolAddress((void**)&pht,   g_ht);
    cudaGetSymbolAddress((void**)&pq1,   g_q1);
    cudaGetSymbolAddress((void**)&pq2,   g_q2);
    cudaGetSymbolAddress((void**)&pafin, g_afin);

    cudaFuncSetAttribute(gemm_tc, cudaFuncAttributeMaxDynamicSharedMemorySize, SM_TOTAL);
    cudaFuncSetAttribute(gemm_scores, cudaFuncAttributeMaxDynamicSharedMemorySize, SM_PTOT);

    prep_kernel  <<<4096, 256>>>(ggnn);
    gather_kernel<<<4096, 256>>>(items, emb);
    gemm_tc<<<dim3(1, 64),  256, SM_TOTAL>>>(px,   pgT, pm,  HDIM);     // m = x @ ggnn_w
    scatter_kernel<<<NEDGE, 128>>>(eidx);
    gemm_tc<<<dim3(3, 64),  256, SM_TOTAL>>>(pagg, Wih, pgi, 3*HDIM);   // gi
    gemm_tc<<<dim3(3, 64),  256, SM_TOTAL>>>(px,   Whh, pgh, 3*HDIM);   // gh
    gru_kernel   <<<4096, 256>>>(bih, bhh);
    hidden_kernel<<<BATCH, 128>>>(items, seq, mask, emb);
    gemm_tc<<<dim3(1, 4),   256, SM_TOTAL>>>(pht,  W1,  pq1, HDIM);     // q1
    gemm_tc<<<dim3(1, 80),  256, SM_TOTAL>>>(phid, W2,  pq2, HDIM);     // q2
    attn_kernel  <<<BATCH, 128>>>(mask, b1, b2, w3, Wt, bt, gamma, beta);
    gemm_scores<<<PGRID, 256, SM_PTOT>>>(pafin, emb + HDIM, out);       // scores
}

// round 11
// speedup vs baseline: 2.3322x; 1.1419x over previous
#include <cuda_runtime.h>
#include <cuda_bf16.h>
#include <math.h>
#include <cstdint>

// ---------------- problem constants ----------------
#define BATCH 512
#define SEQL  20
#define NNODE 16
#define EPS_  32
#define HDIM  128
#define VOCAB 100000
#define NTOT  (BATCH*NNODE)        // 8192
#define NEDGE (BATCH*EPS_)         // 16384
#define NOUT  (VOCAB-1)            // 99999
#define NT_   782                  // ceil(NOUT/128)
#define NPAD  (NT_*128)            // 100096 padded B rows
#define NJOBS (4*NT_)              // 3128
#define PGRID 148

// ---------------- device scratch (no allocs allowed) ----------------
__device__ float g_x[NTOT*HDIM];
__device__ float g_m[NTOT*HDIM];
__device__ float g_agg[NTOT*HDIM];
__device__ float g_gi[NTOT*3*HDIM];
__device__ float g_gh[NTOT*3*HDIM];
__device__ float g_gT[HDIM*HDIM];
__device__ float g_w1T[HDIM*HDIM];
__device__ float g_w2T[HDIM*HDIM];
__device__ float g_wtT[2*HDIM*HDIM];
__device__ __nv_bfloat16 g_bhi[(size_t)NPAD*HDIM];   // emb[1:] hi split (padded)
__device__ __nv_bfloat16 g_blo[(size_t)NPAD*HDIM];   // emb[1:] lo split
__device__ __nv_bfloat16 g_ahi[BATCH*HDIM];          // afin hi split
__device__ __nv_bfloat16 g_alo[BATCH*HDIM];          // afin lo split

// ---------------- helpers ----------------
__device__ __forceinline__ uint32_t smem_to_u32(const void* p) {
    uint32_t a;
    asm("{ .reg .u64 t; cvta.to.shared.u64 t, %1; cvt.u32.u64 %0, t; }" : "=r"(a) : "l"(p));
    return a;
}

// hi = bf16 bits via truncation; lo = RN(x - hi)  (exact 16+8-bit split)
__device__ __forceinline__ void split2(float x, float y, uint32_t& hi, uint32_t& lo) {
    uint32_t ux = __float_as_uint(x), uy = __float_as_uint(y);
    hi = __byte_perm(ux, uy, 0x7632);
    float lx = x - __uint_as_float(ux & 0xffff0000u);
    float ly = y - __uint_as_float(uy & 0xffff0000u);
    __nv_bfloat162 t = __floats2bfloat162_rn(lx, ly);
    lo = *reinterpret_cast<uint32_t*>(&t);
}

#define MMA_BF16(d, a, b)                                                        \
    asm volatile("mma.sync.aligned.m16n8k16.row.col.f32.bf16.bf16.f32 "         \
                 "{%0,%1,%2,%3}, {%4,%5,%6,%7}, {%8,%9}, {%0,%1,%2,%3};"        \
                 : "+f"((d)[0]), "+f"((d)[1]), "+f"((d)[2]), "+f"((d)[3])        \
                 : "r"((a)[0]), "r"((a)[1]), "r"((a)[2]), "r"((a)[3]),           \
                   "r"((b)[0]), "r"((b)[1]))

#define CP_ASYNC16(daddr, gptr) \
    asm volatile("cp.async.cg.shared.global [%0], [%1], 16;" :: "r"(daddr), "l"(gptr))
#define CP_COMMIT() asm volatile("cp.async.commit_group;" ::: "memory")
#define CP_WAIT0()  asm volatile("cp.async.wait_group 0;"  ::: "memory")
#define CP_WAIT1()  asm volatile("cp.async.wait_group 1;"  ::: "memory")

// padded bf16 tile: 128 rows x 128 cols, row pitch 272B -> conflict-free frags
#define ROWB     272
#define TILE_B   34816          // 128*272

// shared MMA inner loop: 128x128x128 split-bf16, 3 passes, 8 warps (2x4)
__device__ __forceinline__ void mma_compute(
    const char* aHb, const char* aLb, const char* bHb, const char* bLb,
    int wm, int wn, int g, int tig, float acc[4][4][4])
{
    const char* aH = aHb + (uint32_t)(wm * 64 + g) * ROWB + tig * 4;
    const char* aL = aLb + (uint32_t)(wm * 64 + g) * ROWB + tig * 4;
    const char* bH = bHb + (uint32_t)(wn * 32 + g) * ROWB + tig * 4;
    const char* bL = bLb + (uint32_t)(wn * 32 + g) * ROWB + tig * 4;

    #pragma unroll
    for (int ks = 0; ks < 8; ++ks) {
        const int kb = ks * 32;
        uint32_t ah[4][4], bh[4][2];
        #pragma unroll
        for (int mf = 0; mf < 4; ++mf) {
            const char* p = aH + mf * (16 * ROWB) + kb;
            ah[mf][0] = *reinterpret_cast<const uint32_t*>(p);
            ah[mf][1] = *reinterpret_cast<const uint32_t*>(p + 8 * ROWB);
            ah[mf][2] = *reinterpret_cast<const uint32_t*>(p + 16);
            ah[mf][3] = *reinterpret_cast<const uint32_t*>(p + 8 * ROWB + 16);
        }
        #pragma unroll
        for (int nf = 0; nf < 4; ++nf) {
            const char* p = bH + nf * (8 * ROWB) + kb;
            bh[nf][0] = *reinterpret_cast<const uint32_t*>(p);
            bh[nf][1] = *reinterpret_cast<const uint32_t*>(p + 16);
        }
        #pragma unroll
        for (int mf = 0; mf < 4; ++mf)
            #pragma unroll
            for (int nf = 0; nf < 4; ++nf)
                MMA_BF16(acc[mf][nf], ah[mf], bh[nf]);

        uint32_t bl[4][2];
        #pragma unroll
        for (int nf = 0; nf < 4; ++nf) {
            const char* p = bL + nf * (8 * ROWB) + kb;
            bl[nf][0] = *reinterpret_cast<const uint32_t*>(p);
            bl[nf][1] = *reinterpret_cast<const uint32_t*>(p + 16);
        }
        #pragma unroll
        for (int mf = 0; mf < 4; ++mf)
            #pragma unroll
            for (int nf = 0; nf < 4; ++nf)
                MMA_BF16(acc[mf][nf], ah[mf], bl[nf]);

        uint32_t al[4][4];
        #pragma unroll
        for (int mf = 0; mf < 4; ++mf) {
            const char* p = aL + mf * (16 * ROWB) + kb;
            al[mf][0] = *reinterpret_cast<const uint32_t*>(p);
            al[mf][1] = *reinterpret_cast<const uint32_t*>(p + 8 * ROWB);
            al[mf][2] = *reinterpret_cast<const uint32_t*>(p + 16);
            al[mf][3] = *reinterpret_cast<const uint32_t*>(p + 8 * ROWB + 16);
        }
        #pragma unroll
        for (int mf = 0; mf < 4; ++mf)
            #pragma unroll
            for (int nf = 0; nf < 4; ++nf)
                MMA_BF16(acc[mf][nf], al[mf], bh[nf]);
    }
}

// ---------------- generic small GEMM: fp32 in, split in-kernel ----------------
#define SM_AHI   0
#define SM_ALO   34816
#define SM_BHI   69632
#define SM_BLO   104448
#define SM_TOTAL 139264

__device__ __forceinline__ void gemm_tile_body(
    const float* __restrict__ A, const float* __restrict__ B,
    float* __restrict__ C, int N, int mBase, int nBase, char* sm)
{
    const int tid  = threadIdx.x, wid = tid >> 5, lane = tid & 31;
    const int g    = lane >> 2, tig = lane & 3;

    #pragma unroll
    for (int it = 0; it < 16; ++it) {
        int idx = tid + it * 256;
        int r = idx >> 5, c4 = (idx & 31) << 2;
        uint32_t soff = (uint32_t)r * ROWB + (uint32_t)c4 * 2;

        float4 v = *reinterpret_cast<const float4*>(A + (size_t)(mBase + r) * 128 + c4);
        uint32_t h0, l0, h1, l1;
        split2(v.x, v.y, h0, l0);
        split2(v.z, v.w, h1, l1);
        *reinterpret_cast<uint2*>(sm + SM_AHI + soff) = make_uint2(h0, h1);
        *reinterpret_cast<uint2*>(sm + SM_ALO + soff) = make_uint2(l0, l1);

        int n = nBase + r;
        float4 w = make_float4(0.f, 0.f, 0.f, 0.f);
        if (n < N) w = *reinterpret_cast<const float4*>(B + (size_t)n * 128 + c4);
        split2(w.x, w.y, h0, l0);
        split2(w.z, w.w, h1, l1);
        *reinterpret_cast<uint2*>(sm + SM_BHI + soff) = make_uint2(h0, h1);
        *reinterpret_cast<uint2*>(sm + SM_BLO + soff) = make_uint2(l0, l1);
    }
    __syncthreads();

    const int wm = wid >> 2, wn = wid & 3;
    float acc[4][4][4];
    #pragma unroll
    for (int mf = 0; mf < 4; ++mf)
        #pragma unroll
        for (int nf = 0; nf < 4; ++nf)
            #pragma unroll
            for (int e = 0; e < 4; ++e) acc[mf][nf][e] = 0.f;

    mma_compute(sm + SM_AHI, sm + SM_ALO, sm + SM_BHI, sm + SM_BLO,
                wm, wn, g, tig, acc);

    #pragma unroll
    for (int mf = 0; mf < 4; ++mf) {
        int row0 = mBase + wm * 64 + mf * 16 + g;
        #pragma unroll
        for (int nf = 0; nf < 4; ++nf) {
            int col = nBase + wn * 32 + nf * 8 + tig * 2;
            if (col + 1 < N) {
                C[(size_t)row0 * N + col]           = acc[mf][nf][0];
                C[(size_t)row0 * N + col + 1]       = acc[mf][nf][1];
                C[(size_t)(row0 + 8) * N + col]     = acc[mf][nf][2];
                C[(size_t)(row0 + 8) * N + col + 1] = acc[mf][nf][3];
            } else if (col < N) {
                C[(size_t)row0 * N + col]       = acc[mf][nf][0];
                C[(size_t)(row0 + 8) * N + col] = acc[mf][nf][2];
            }
        }
    }
}

__global__ __launch_bounds__(256) void gemm_tc(
    const float* __restrict__ A, const float* __restrict__ B,
    float* __restrict__ C, int N)
{
    extern __shared__ char sm[];
    gemm_tile_body(A, B, C, N, blockIdx.y << 7, blockIdx.x << 7, sm);
}

// fused gi/gh: grid (6, 64); bx<3 -> gi = agg@Wih^T, else gh = x@Whh^T
__global__ __launch_bounds__(256) void gemm_gates(
    const float* __restrict__ Wih, const float* __restrict__ Whh)
{
    extern __shared__ char sm[];
    int sel = blockIdx.x / 3, nb = blockIdx.x % 3;
    const float* A = sel ? g_x : g_agg;
    const float* B = sel ? Whh : Wih;
    float*       C = sel ? g_gh : g_gi;
    gemm_tile_body(A, B, C, 3 * HDIM, blockIdx.y << 7, nb << 7, sm);
}

// ---------------- persistent vocab GEMM (pre-split bf16, double-buffered) ----------------
#define SB(p)    (TILE_B * 2 + (p) * (TILE_B * 2))   // B buffer p base (69632 / 139264)
#define SM_PTOT  (TILE_B * 6)                         // 208896
#define PADF     132

__device__ __forceinline__ void ld_tile_bf16(
    const __nv_bfloat16* __restrict__ src, int row0, uint32_t dstbase, int tid)
{
    #pragma unroll
    for (int it = 0; it < 8; ++it) {
        int idx = tid + it * 256;          // 0..2047 chunks of 16B
        int r = idx >> 4, c16 = idx & 15;
        uint32_t daddr = dstbase + (uint32_t)r * ROWB + c16 * 16;
        CP_ASYNC16(daddr, src + (size_t)(row0 + r) * 128 + c16 * 8);
    }
}

__global__ __launch_bounds__(256) void gemm_scores(float* __restrict__ C)
{
    extern __shared__ char sm[];
    uint32_t smb = smem_to_u32(sm);
    const int tid = threadIdx.x, wid = tid >> 5, lane = tid & 31;
    const int g = lane >> 2, tig = lane & 3;
    const int wm = wid >> 2, wn = wid & 3;

    int m_cur = blockIdx.x / NT_;   // = 0 for all (148 < 782), generic anyway
    // initial loads: A(m_cur) and B(job0)
    ld_tile_bf16(g_ahi, m_cur << 7, smb + 0,      tid);
    ld_tile_bf16(g_alo, m_cur << 7, smb + TILE_B, tid);
    CP_COMMIT();
    {
        int n0 = blockIdx.x - m_cur * NT_;
        ld_tile_bf16(g_bhi, n0 << 7, smb + SB(0),          tid);
        ld_tile_bf16(g_blo, n0 << 7, smb + SB(0) + TILE_B, tid);
        CP_COMMIT();
    }
    int p = 0;

    for (int j = blockIdx.x; j < NJOBS; j += PGRID) {
        const int n = j - m_cur * NT_;
        const int jn = j + PGRID;
        const bool havenext = jn < NJOBS;
        const int mn = havenext ? jn / NT_ : -1;

        bool pfx = false;
        if (havenext && mn == m_cur) {
            int nn = jn - mn * NT_;
            ld_tile_bf16(g_bhi, nn << 7, smb + SB(1 - p),          tid);
            ld_tile_bf16(g_blo, nn << 7, smb + SB(1 - p) + TILE_B, tid);
            CP_COMMIT();
            pfx = true;
        }
        if (pfx) { CP_WAIT1(); } else { CP_WAIT0(); }
        __syncthreads();

        float acc[4][4][4];
        #pragma unroll
        for (int mf = 0; mf < 4; ++mf)
            #pragma unroll
            for (int nf = 0; nf < 4; ++nf)
                #pragma unroll
                for (int e = 0; e < 4; ++e) acc[mf][nf][e] = 0.f;

        mma_compute(sm + 0, sm + TILE_B, sm + SB(p), sm + SB(p) + TILE_B,
                    wm, wn, g, tig, acc);

        // epilogue: fragments -> smem (reuse just-consumed buf p) -> coalesced STG
        __syncthreads();
        float* eb = reinterpret_cast<float*>(sm + SB(p));
        #pragma unroll
        for (int mf = 0; mf < 4; ++mf) {
            int rl = wm * 64 + mf * 16 + g;
            #pragma unroll
            for (int nf = 0; nf < 4; ++nf) {
                int cl = wn * 32 + nf * 8 + tig * 2;
                *reinterpret_cast<float2*>(&eb[rl * PADF + cl]) =
                    make_float2(acc[mf][nf][0], acc[mf][nf][1]);
                *reinterpret_cast<float2*>(&eb[(rl + 8) * PADF + cl]) =
                    make_float2(acc[mf][nf][2], acc[mf][nf][3]);
            }
        }
        __syncthreads();
        {
            const int mB = m_cur << 7, nB = n << 7;
            #pragma unroll 4
            for (int k = tid; k < 128 * 128; k += 256) {
                int r = k >> 7, c = k & 127;
                int col = nB + c;
                if (col < NOUT) C[(size_t)(mB + r) * NOUT + col] = eb[r * PADF + c];
            }
        }

        if (havenext && mn != m_cur) {
            m_cur = mn;
            ld_tile_bf16(g_ahi, m_cur << 7, smb + 0,      tid);
            ld_tile_bf16(g_alo, m_cur << 7, smb + TILE_B, tid);
            CP_COMMIT();
            int nn = jn - mn * NT_;
            ld_tile_bf16(g_bhi, nn << 7, smb + SB(1 - p),          tid);
            ld_tile_bf16(g_blo, nn << 7, smb + SB(1 - p) + TILE_B, tid);
            CP_COMMIT();
        }
        p ^= 1;
    }
}

// ---------------- prep: zero agg, transposes, emb split, x gather ----------------
__global__ void prep_kernel(const int* __restrict__ items,
                            const float* __restrict__ emb,
                            const float* __restrict__ ggnn,
                            const float* __restrict__ W1,
                            const float* __restrict__ W2,
                            const float* __restrict__ Wt) {
    int i = blockIdx.x * 256 + threadIdx.x;
    if (i < NPAD * HDIM) {                     // emb[1:] split, zero-padded rows
        int n = i >> 7, c = i & 127;
        float v = (n < NOUT) ? emb[(size_t)(n + 1) * 128 + c] : 0.f;
        uint32_t u = __float_as_uint(v);
        __nv_bfloat16_raw hr; hr.x = (unsigned short)(u >> 16);
        g_bhi[i] = __nv_bfloat16(hr);
        g_blo[i] = __float2bfloat16(v - __uint_as_float(u & 0xffff0000u));
    }
    if (i < NTOT * HDIM) {
        g_agg[i] = 0.f;
        int node = i >> 7, h = i & 127;
        g_x[i] = emb[(size_t)items[node] * 128 + h];
    }
    if (i < HDIM * HDIM) {                     // i = row*128 + col of source
        int r = i >> 7, c = i & 127;
        g_gT[c * 128 + r]  = ggnn[i];          // ggnn[k][h] -> gT[h][k]
        g_w1T[c * 128 + r] = W1[i];            // W1[h][k]  -> w1T[k][h]
        g_w2T[c * 128 + r] = W2[i];
    }
    if (i < 2 * HDIM * HDIM) {                 // Wt [128][256]
        int r = i >> 8, c = i & 255;
        g_wtT[c * 128 + r] = Wt[i];            // wtT[k][h]
    }
}

__global__ void scatter_kernel(const int* __restrict__ ei) {
    int e = blockIdx.x;
    int h = threadIdx.x;
    int s = ei[e], d = ei[NEDGE + e];
    atomicAdd(&g_agg[(size_t)d * HDIM + h], g_m[(size_t)s * HDIM + h]);
}

// ---------------- fused GRU + hidden + attention + transform + LN ----------------
__device__ __forceinline__ float blockSum128(float v, float* red) {
    #pragma unroll
    for (int o = 16; o > 0; o >>= 1) v += __shfl_xor_sync(0xffffffffu, v, o);
    if ((threadIdx.x & 31) == 0) red[threadIdx.x >> 5] = v;
    __syncthreads();
    v = red[0] + red[1] + red[2] + red[3];
    __syncthreads();
    return v;
}

__global__ __launch_bounds__(128) void attn_kernel(
    const int* __restrict__ items, const int* __restrict__ seq,
    const int* __restrict__ mask,  const float* __restrict__ emb,
    const float* __restrict__ bih, const float* __restrict__ bhh,
    const float* __restrict__ b1,  const float* __restrict__ b2,
    const float* __restrict__ w3,  const float* __restrict__ bt,
    const float* __restrict__ gamma, const float* __restrict__ beta)
{
    int b = blockIdx.x, h = threadIdx.x;
    __shared__ float xg[NNODE][HDIM];
    __shared__ float hid[SEQL][HDIM];
    __shared__ float a_s[HDIM], ht_s[HDIM];
    __shared__ float red[4];
    __shared__ int it_s[NNODE];
    __shared__ int msk[SEQL];
    __shared__ int sl;

    if (h < NNODE) it_s[h] = items[b * NNODE + h];
    if (h < SEQL)  msk[h]  = mask[b * SEQL + h];
    if (h == 0) {
        int c = 0;
        for (int l = 0; l < SEQL; ++l) c += mask[b * SEQL + l];
        sl = c - 1;
    }
    __syncthreads();

    // GRU for this session's 16 nodes
    float bi0 = bih[h], bi1 = bih[128 + h], bi2 = bih[256 + h];
    float bh0 = bhh[h], bh1 = bhh[128 + h], bh2 = bhh[256 + h];
    #pragma unroll 4
    for (int ni = 0; ni < NNODE; ++ni) {
        size_t node = (size_t)b * NNODE + ni;
        const float* gi = g_gi + node * 384;
        const float* gh = g_gh + node * 384;
        float r = 1.f / (1.f + expf(-((gi[h] + bi0) + (gh[h] + bh0))));
        float z = 1.f / (1.f + expf(-((gi[128 + h] + bi1) + (gh[128 + h] + bh1))));
        float nn = tanhf((gi[256 + h] + bi2) + r * (gh[256 + h] + bh2));
        float xo = g_x[node * HDIM + h];
        xg[ni][h] = (1.f - z) * nn + z * xo;
    }
    __syncthreads();

    // hidden gather
    for (int l = 0; l < SEQL; ++l) {
        int s = seq[b * SEQL + l];
        float v = 0.f;
        if (s != 0) {
            int found = -1;
            #pragma unroll
            for (int ni = 0; ni < NNODE; ++ni)
                if (found < 0 && it_s[ni] == s) found = ni;
            v = (found >= 0) ? xg[found][h] : emb[(size_t)s * HDIM + h];
        }
        hid[l][h] = v;
    }
    __syncthreads();
    ht_s[h] = hid[sl][h];
    __syncthreads();

    // q1 = ht @ W1^T
    float q1v = b1[h];
    #pragma unroll 8
    for (int k = 0; k < HDIM; ++k) q1v += ht_s[k] * g_w1T[k * 128 + h];

    // attention
    float w3v = w3[h];
    float acc = 0.f;
    for (int l = 0; l < SEQL; ++l) {
        float q2v = b2[h];
        #pragma unroll 8
        for (int k = 0; k < HDIM; ++k) q2v += hid[l][k] * g_w2T[k * 128 + h];
        float s = 1.f / (1.f + expf(-(q1v + q2v)));
        float alpha = blockSum128(s * w3v, red);
        if (msk[l]) acc += alpha * hid[l][h];
    }
    a_s[h] = acc;
    __syncthreads();

    // hybrid transform + layernorm
    float av = bt[h];
    #pragma unroll 8
    for (int k = 0; k < HDIM; ++k) av += a_s[k]  * g_wtT[k * 128 + h];
    #pragma unroll 8
    for (int k = 0; k < HDIM; ++k) av += ht_s[k] * g_wtT[(128 + k) * 128 + h];

    float mu  = blockSum128(av, red) * (1.f / HDIM);
    float d   = av - mu;
    float var = blockSum128(d * d, red) * (1.f / HDIM);
    float v   = d * rsqrtf(var + 1e-5f) * gamma[h] + beta[h];

    // emit pre-split afin
    uint32_t u = __float_as_uint(v);
    __nv_bfloat16_raw hr; hr.x = (unsigned short)(u >> 16);
    g_ahi[b * HDIM + h] = __nv_bfloat16(hr);
    g_alo[b * HDIM + h] = __float2bfloat16(v - __uint_as_float(u & 0xffff0000u));
}

// ---------------- launch ----------------
extern "C" void kernel_launch(void* const* d_in, const int* in_sizes, int n_in,
                              void* d_out, int out_size) {
    const int*   items = (const int*)  d_in[0];
    const int*   eidx  = (const int*)  d_in[1];
    const int*   seq   = (const int*)  d_in[2];
    const int*   mask  = (const int*)  d_in[3];
    const float* emb   = (const float*)d_in[4];
    const float* ggnn  = (const float*)d_in[5];
    const float* Wih   = (const float*)d_in[6];
    const float* Whh   = (const float*)d_in[7];
    const float* bih   = (const float*)d_in[8];
    const float* bhh   = (const float*)d_in[9];
    const float* W1    = (const float*)d_in[10];
    const float* b1    = (const float*)d_in[11];
    const float* W2    = (const float*)d_in[12];
    const float* b2    = (const float*)d_in[13];
    const float* w3    = (const float*)d_in[14];
    const float* Wt    = (const float*)d_in[15];
    const float* bt    = (const float*)d_in[16];
    const float* gamma = (const float*)d_in[17];
    const float* beta  = (const float*)d_in[18];
    float* out = (float*)d_out;

    float *px, *pgT;
    cudaGetSymbolAddress((void**)&px,  g_x);
    cudaGetSymbolAddress((void**)&pgT, g_gT);
    float* pm;
    cudaGetSymbolAddress((void**)&pm,  g_m);

    cudaFuncSetAttribute(gemm_tc,     cudaFuncAttributeMaxDynamicSharedMemorySize, SM_TOTAL);
    cudaFuncSetAttribute(gemm_gates,  cudaFuncAttributeMaxDynamicSharedMemorySize, SM_TOTAL);
    cudaFuncSetAttribute(gemm_scores, cudaFuncAttributeMaxDynamicSharedMemorySize, SM_PTOT);

    const int prep_grid = (NPAD * HDIM + 255) / 256;      // 50048

    prep_kernel<<<prep_grid, 256>>>(items, emb, ggnn, W1, W2, Wt);        // 0
    gemm_tc<<<dim3(1, 64), 256, SM_TOTAL>>>(px, pgT, pm, HDIM);           // 1: m = x @ ggnn_w
    scatter_kernel<<<NEDGE, 128>>>(eidx);                                 // 2
    gemm_gates<<<dim3(6, 64), 256, SM_TOTAL>>>(Wih, Whh);                 // 3: gi + gh
    attn_kernel<<<BATCH, 128>>>(items, seq, mask, emb, bih, bhh,          // 4
                                b1, b2, w3, bt, gamma, beta);
    gemm_scores<<<PGRID, 256, SM_PTOT>>>(out);                            // 5
}